// round 2
// baseline (speedup 1.0000x reference)
#include <cuda_runtime.h>
#include <cuda_bf16.h>

#define NN 4096
#define DIMN 128
#define NH 8
#define ALPHA 0.2f

// Scratch (device globals; no allocation allowed)
__device__ float g_Wh[(size_t)NH * NN * DIMN];   // [h][n][d]
__device__ float g_att[(size_t)NH * NN * DIMN];  // elu(att @ Wh), [h][n][d]
__device__ float g_f1[NH * NN];
__device__ float g_f2[NH * NN];

// ---------------------------------------------------------------------------
// Kernel 1: Wh[h] = nodes @ W[h];  f1[h,n] = Wh[h,n,:]·a1[h]; f2 likewise.
// Block: 256 threads -> 64 rows x 128 cols tile (thread microtile 4x8).
// ---------------------------------------------------------------------------
__global__ __launch_bounds__(256) void k_wh(const float* __restrict__ nodes,
                                            const float* __restrict__ W,
                                            const float* __restrict__ a1,
                                            const float* __restrict__ a2) {
    const int i0 = blockIdx.x * 64;
    const int h  = blockIdx.y;
    __shared__ float As[16][64];    // As[k][r] (transposed for float4 row reads)
    __shared__ float Bs[16][128];

    const int tid = threadIdx.x;
    const int tr = tid >> 4, tc = tid & 15;
    const int r0 = tr * 4, c0 = tc * 8;

    float acc[4][8];
#pragma unroll
    for (int i = 0; i < 4; i++)
#pragma unroll
        for (int j = 0; j < 8; j++) acc[i][j] = 0.f;

    const float* Wp = W + (size_t)h * DIMN * DIMN;
    const int lr = tid >> 2;          // 0..63 (A-load row)
    const int kq = (tid & 3) * 4;     // 0..12 (A-load k base)

    for (int k0 = 0; k0 < DIMN; k0 += 16) {
        float4 av = *(const float4*)(nodes + (size_t)(i0 + lr) * DIMN + k0 + kq);
        As[kq + 0][lr] = av.x; As[kq + 1][lr] = av.y;
        As[kq + 2][lr] = av.z; As[kq + 3][lr] = av.w;
        float4 b0 = *(const float4*)(Wp + (size_t)(k0 + tr) * DIMN + c0);
        float4 b1 = *(const float4*)(Wp + (size_t)(k0 + tr) * DIMN + c0 + 4);
        *(float4*)&Bs[tr][c0]     = b0;
        *(float4*)&Bs[tr][c0 + 4] = b1;
        __syncthreads();
#pragma unroll
        for (int kk = 0; kk < 16; kk++) {
            float4 a4 = *(float4*)&As[kk][r0];
            float ar[4] = {a4.x, a4.y, a4.z, a4.w};
            float4 u = *(float4*)&Bs[kk][c0];
            float4 v = *(float4*)&Bs[kk][c0 + 4];
            float br[8] = {u.x, u.y, u.z, u.w, v.x, v.y, v.z, v.w};
#pragma unroll
            for (int i = 0; i < 4; i++)
#pragma unroll
                for (int j = 0; j < 8; j++) acc[i][j] += ar[i] * br[j];
        }
        __syncthreads();
    }

    // Epilogue: store Wh, reduce f1/f2 across the 16-thread row group.
    float a1v[8], a2v[8];
#pragma unroll
    for (int j = 0; j < 8; j++) {
        a1v[j] = a1[h * DIMN + c0 + j];
        a2v[j] = a2[h * DIMN + c0 + j];
    }
#pragma unroll
    for (int i = 0; i < 4; i++) {
        const int row = i0 + r0 + i;
        float s1 = 0.f, s2 = 0.f;
#pragma unroll
        for (int j = 0; j < 8; j++) {
            s1 += acc[i][j] * a1v[j];
            s2 += acc[i][j] * a2v[j];
        }
#pragma unroll
        for (int m = 8; m >= 1; m >>= 1) {
            s1 += __shfl_xor_sync(0xffffffffu, s1, m);
            s2 += __shfl_xor_sync(0xffffffffu, s2, m);
        }
        if (tc == 0) {
            g_f1[h * NN + row] = s1;
            g_f2[h * NN + row] = s2;
        }
        float* dst = g_Wh + ((size_t)h * NN + row) * DIMN + c0;
        *(float4*)dst       = make_float4(acc[i][0], acc[i][1], acc[i][2], acc[i][3]);
        *(float4*)(dst + 4) = make_float4(acc[i][4], acc[i][5], acc[i][6], acc[i][7]);
    }
}

// ---------------------------------------------------------------------------
// Kernel 2: masked softmax attention + aggregation, flash-style over j tiles.
// Block tile: 128 i-rows x 128 d-cols, 256 threads, 8x8 microtile.
// For each (h, i-tile): loop j tiles of 64:
//   p[r][c] = adj[i,j] ? exp(leaky(f1[i]+f2[j])) : 0   (no max-shift needed:
//   scores are O(1); exp never overflows; exp(-9e15)==0 matches mask exactly)
//   acc += p @ Wh[j-tile];  den[r] += row-sum(p) folded into GEMM A-reads.
// Output: g_att = elu(acc/den).
// ---------------------------------------------------------------------------
__global__ __launch_bounds__(256, 2) void k_attn(const int* __restrict__ adj) {
    const int i0 = blockIdx.x * 128;
    const int h  = blockIdx.y;
    __shared__ float pT[64][128];   // pT[jc][ir]  (transposed p tile)  32KB
    __shared__ float Bs[64][128];   // Wh j-tile                        32KB

    const int tid = threadIdx.x;
    const int tr = tid >> 4, tc = tid & 15;
    const int r0 = tr * 8, c0 = tc * 8;

    const int pr = tid >> 1;            // 0..127 : p-gen row
    const int pc = (tid & 1) << 5;      // 0/32   : p-gen col base
    const float f1v = g_f1[h * NN + i0 + pr];
    const int* adjRow = adj + (size_t)(i0 + pr) * NN;
    const float* f2base = g_f2 + h * NN;

    float acc[8][8];
#pragma unroll
    for (int i = 0; i < 8; i++)
#pragma unroll
        for (int j = 0; j < 8; j++) acc[i][j] = 0.f;
    float den[8] = {0.f, 0.f, 0.f, 0.f, 0.f, 0.f, 0.f, 0.f};

    for (int j0 = 0; j0 < NN; j0 += 64) {
        __syncthreads();
        // --- generate p tile: 32 elements/thread ---
#pragma unroll
        for (int b = 0; b < 8; b++) {
            int4 aj = *(const int4*)(adjRow + j0 + pc + b * 4);
            float4 f2v = *(const float4*)(f2base + j0 + pc + b * 4);
            float e, p;
            e = f1v + f2v.x; e = e > 0.f ? e : ALPHA * e;
            p = (aj.x > 0) ? __expf(e) : 0.f; pT[pc + b * 4 + 0][pr] = p;
            e = f1v + f2v.y; e = e > 0.f ? e : ALPHA * e;
            p = (aj.y > 0) ? __expf(e) : 0.f; pT[pc + b * 4 + 1][pr] = p;
            e = f1v + f2v.z; e = e > 0.f ? e : ALPHA * e;
            p = (aj.z > 0) ? __expf(e) : 0.f; pT[pc + b * 4 + 2][pr] = p;
            e = f1v + f2v.w; e = e > 0.f ? e : ALPHA * e;
            p = (aj.w > 0) ? __expf(e) : 0.f; pT[pc + b * 4 + 3][pr] = p;
        }
        // --- load Wh tile [64][128] (8 float4 per thread) ---
        const float* whp = g_Wh + ((size_t)h * NN + j0) * DIMN;
#pragma unroll
        for (int q = 0; q < 8; q++) {
            int idx = tid + q * 256;
            int rr = idx >> 5;
            int cc = (idx & 31) << 2;
            *(float4*)&Bs[rr][cc] = *(const float4*)(whp + (size_t)rr * DIMN + cc);
        }
        __syncthreads();
        // --- GEMM: acc[128x128] += p[128x64] @ Wh[64x128]; den from A reads ---
#pragma unroll 4
        for (int kk = 0; kk < 64; kk++) {
            float4 a0 = *(float4*)&pT[kk][r0];
            float4 a1_ = *(float4*)&pT[kk][r0 + 4];
            float ar[8] = {a0.x, a0.y, a0.z, a0.w, a1_.x, a1_.y, a1_.z, a1_.w};
#pragma unroll
            for (int i = 0; i < 8; i++) den[i] += ar[i];
            float4 u = *(float4*)&Bs[kk][c0];
            float4 v = *(float4*)&Bs[kk][c0 + 4];
            float br[8] = {u.x, u.y, u.z, u.w, v.x, v.y, v.z, v.w};
#pragma unroll
            for (int i = 0; i < 8; i++)
#pragma unroll
                for (int j = 0; j < 8; j++) acc[i][j] += ar[i] * br[j];
        }
    }

    // Epilogue: normalize, ELU, store
#pragma unroll
    for (int i = 0; i < 8; i++) {
        const int row = i0 + r0 + i;
        const float inv = 1.0f / den[i];
        float o[8];
#pragma unroll
        for (int j = 0; j < 8; j++) {
            float v = acc[i][j] * inv;
            o[j] = v > 0.f ? v : expm1f(v);
        }
        float* dst = g_att + ((size_t)h * NN + row) * DIMN + c0;
        *(float4*)dst       = make_float4(o[0], o[1], o[2], o[3]);
        *(float4*)(dst + 4) = make_float4(o[4], o[5], o[6], o[7]);
    }
}

// ---------------------------------------------------------------------------
// Kernel 3: x = elu(cat @ W1 + b1);  out = layernorm(nodes + x)
// cat[n, h*128+d] = g_att[h][n][d].  Tile 64x128, K=1024 in chunks of 16.
// ---------------------------------------------------------------------------
__global__ __launch_bounds__(256) void k_out(const float* __restrict__ nodes,
                                             const float* __restrict__ W1,
                                             const float* __restrict__ b1,
                                             const float* __restrict__ gamma,
                                             const float* __restrict__ beta,
                                             float* __restrict__ out) {
    const int i0 = blockIdx.x * 64;
    __shared__ float As[16][64];
    __shared__ float Bs[16][128];

    const int tid = threadIdx.x;
    const int tr = tid >> 4, tc = tid & 15;
    const int r0 = tr * 4, c0 = tc * 8;
    const int lr = tid >> 2;
    const int kq = (tid & 3) * 4;

    float acc[4][8];
#pragma unroll
    for (int i = 0; i < 4; i++)
#pragma unroll
        for (int j = 0; j < 8; j++) acc[i][j] = 0.f;

    for (int k0 = 0; k0 < NH * DIMN; k0 += 16) {
        const int hh = k0 >> 7;
        const int db = k0 & 127;
        float4 av = *(const float4*)(g_att + ((size_t)hh * NN + i0 + lr) * DIMN + db + kq);
        As[kq + 0][lr] = av.x; As[kq + 1][lr] = av.y;
        As[kq + 2][lr] = av.z; As[kq + 3][lr] = av.w;
        float4 b0 = *(const float4*)(W1 + (size_t)(k0 + tr) * DIMN + c0);
        float4 b4 = *(const float4*)(W1 + (size_t)(k0 + tr) * DIMN + c0 + 4);
        *(float4*)&Bs[tr][c0]     = b0;
        *(float4*)&Bs[tr][c0 + 4] = b4;
        __syncthreads();
#pragma unroll
        for (int kk = 0; kk < 16; kk++) {
            float4 a4 = *(float4*)&As[kk][r0];
            float ar[4] = {a4.x, a4.y, a4.z, a4.w};
            float4 u = *(float4*)&Bs[kk][c0];
            float4 v = *(float4*)&Bs[kk][c0 + 4];
            float br[8] = {u.x, u.y, u.z, u.w, v.x, v.y, v.z, v.w};
#pragma unroll
            for (int i = 0; i < 4; i++)
#pragma unroll
                for (int j = 0; j < 8; j++) acc[i][j] += ar[i] * br[j];
        }
        __syncthreads();
    }

    float bb[8], gg[8], be[8];
#pragma unroll
    for (int j = 0; j < 8; j++) {
        bb[j] = b1[c0 + j];
        gg[j] = gamma[c0 + j];
        be[j] = beta[c0 + j];
    }

#pragma unroll
    for (int i = 0; i < 4; i++) {
        const int row = i0 + r0 + i;
        float t[8];
        float s = 0.f;
#pragma unroll
        for (int j = 0; j < 8; j++) {
            float v = acc[i][j] + bb[j];
            v = v > 0.f ? v : expm1f(v);
            t[j] = nodes[(size_t)row * DIMN + c0 + j] + v;
            s += t[j];
        }
#pragma unroll
        for (int m = 8; m >= 1; m >>= 1) s += __shfl_xor_sync(0xffffffffu, s, m);
        const float mu = s * (1.0f / 128.0f);
        float q = 0.f;
#pragma unroll
        for (int j = 0; j < 8; j++) {
            float d = t[j] - mu;
            q += d * d;
        }
#pragma unroll
        for (int m = 8; m >= 1; m >>= 1) q += __shfl_xor_sync(0xffffffffu, q, m);
        const float var = q * (1.0f / 128.0f);
        const float rs = rsqrtf(var + 1e-5f);
        float o[8];
#pragma unroll
        for (int j = 0; j < 8; j++) o[j] = (t[j] - mu) * rs * gg[j] + be[j];
        float* dst = out + (size_t)row * DIMN + c0;
        *(float4*)dst       = make_float4(o[0], o[1], o[2], o[3]);
        *(float4*)(dst + 4) = make_float4(o[4], o[5], o[6], o[7]);
    }
}

// ---------------------------------------------------------------------------
extern "C" void kernel_launch(void* const* d_in, const int* in_sizes, int n_in,
                              void* d_out, int out_size) {
    const float* nodes = (const float*)d_in[0];
    const int*   adj   = (const int*)d_in[1];
    const float* W     = (const float*)d_in[2];
    const float* a1    = (const float*)d_in[3];
    const float* a2    = (const float*)d_in[4];
    const float* W1    = (const float*)d_in[5];
    const float* b1    = (const float*)d_in[6];
    const float* gamma = (const float*)d_in[7];
    const float* beta  = (const float*)d_in[8];
    float* out = (float*)d_out;

    dim3 gridWh(NN / 64, NH);
    k_wh<<<gridWh, 256>>>(nodes, W, a1, a2);
    dim3 gridAttn(NN / 128, NH);
    k_attn<<<gridAttn, 256>>>(adj);
    k_out<<<NN / 64, 256>>>(nodes, W1, b1, gamma, beta, out);
}

// round 10
// speedup vs baseline: 2.8177x; 2.8177x over previous
#include <cuda_runtime.h>
#include <cuda_fp16.h>
#include <cstdint>

#define NN 4096
#define DIMN 128
#define NH 8
#define ALPHA 0.2f

// ---------------- device scratch (no allocation allowed) -------------------
__device__ __half g_Whh[(size_t)NH * NN * DIMN];          // [h][n][d] fp16
__device__ float g_att[(size_t)NH * NN * DIMN];           // elu(att @ Wh) fp32
__device__ __half g_E1p[NH * NN];  // exp(min(f1,5.5))
__device__ __half g_E1n[NH * NN];  // exp(0.2*f1)
__device__ __half g_E2p[NH * NN];  // exp(min(f2,5.5))
__device__ __half g_E2n[NH * NN];  // exp(0.2*f2)
__device__ unsigned int g_maskx[(size_t)NN * (NN / 2)];   // 16-bit AND masks, packed x2

// ---------------- helpers ---------------------------------------------------
__device__ __forceinline__ uint32_t smem_u32(const void* p) {
    uint32_t a;
    asm("{ .reg .u64 t; cvta.to.shared.u64 t, %1; cvt.u32.u64 %0, t; }" : "=r"(a) : "l"(p));
    return a;
}
__device__ __forceinline__ void ldsm4(uint32_t& r0, uint32_t& r1, uint32_t& r2,
                                      uint32_t& r3, uint32_t addr) {
    asm volatile("ldmatrix.sync.aligned.m8n8.x4.shared.b16 {%0,%1,%2,%3}, [%4];"
                 : "=r"(r0), "=r"(r1), "=r"(r2), "=r"(r3) : "r"(addr));
}
__device__ __forceinline__ void ldsm4t(uint32_t& r0, uint32_t& r1, uint32_t& r2,
                                       uint32_t& r3, uint32_t addr) {
    asm volatile("ldmatrix.sync.aligned.m8n8.x4.trans.shared.b16 {%0,%1,%2,%3}, [%4];"
                 : "=r"(r0), "=r"(r1), "=r"(r2), "=r"(r3) : "r"(addr));
}
__device__ __forceinline__ void mma16816(float* c, const uint32_t* a,
                                         uint32_t b0, uint32_t b1) {
    asm volatile(
        "mma.sync.aligned.m16n8k16.row.col.f32.f16.f16.f32 "
        "{%0,%1,%2,%3}, {%4,%5,%6,%7}, {%8,%9}, {%0,%1,%2,%3};"
        : "+f"(c[0]), "+f"(c[1]), "+f"(c[2]), "+f"(c[3])
        : "r"(a[0]), "r"(a[1]), "r"(a[2]), "r"(a[3]), "r"(b0), "r"(b1));
}
__device__ __forceinline__ uint32_t h2mulmax(uint32_t e1p, uint32_t e1n,
                                             uint32_t e2p, uint32_t e2n,
                                             uint32_t msk) {
    __half2 u = __hmul2(*(__half2*)&e1p, *(__half2*)&e2p);
    __half2 v = __hmul2(*(__half2*)&e1n, *(__half2*)&e2n);
    __half2 m = __hmax2(u, v);
    return (*(uint32_t*)&m) & msk;
}

// ---------------------------------------------------------------------------
// adj -> packed 16-bit AND masks
// ---------------------------------------------------------------------------
__global__ __launch_bounds__(256) void k_mask(const int* __restrict__ adj) {
    size_t idx = (size_t)blockIdx.x * 256 + threadIdx.x;
    int2 a = ((const int2*)adj)[idx];
    g_maskx[idx] = (a.x > 0 ? 0x0000FFFFu : 0u) | (a.y > 0 ? 0xFFFF0000u : 0u);
}

// ---------------------------------------------------------------------------
// Kernel 1: Wh (fp16) + fused exp tables from f1/f2
// ---------------------------------------------------------------------------
__global__ __launch_bounds__(256) void k_wh(const float* __restrict__ nodes,
                                            const float* __restrict__ W,
                                            const float* __restrict__ a1,
                                            const float* __restrict__ a2) {
    const int i0 = blockIdx.x * 64;
    const int h  = blockIdx.y;
    __shared__ float As[16][64];
    __shared__ float Bs[16][128];

    const int tid = threadIdx.x;
    const int tr = tid >> 4, tc = tid & 15;
    const int r0 = tr * 4, c0 = tc * 8;

    float acc[4][8];
#pragma unroll
    for (int i = 0; i < 4; i++)
#pragma unroll
        for (int j = 0; j < 8; j++) acc[i][j] = 0.f;

    const float* Wp = W + (size_t)h * DIMN * DIMN;
    const int lr = tid >> 2;
    const int kq = (tid & 3) * 4;

    for (int k0 = 0; k0 < DIMN; k0 += 16) {
        float4 av = *(const float4*)(nodes + (size_t)(i0 + lr) * DIMN + k0 + kq);
        As[kq + 0][lr] = av.x; As[kq + 1][lr] = av.y;
        As[kq + 2][lr] = av.z; As[kq + 3][lr] = av.w;
        float4 b0 = *(const float4*)(Wp + (size_t)(k0 + tr) * DIMN + c0);
        float4 b1 = *(const float4*)(Wp + (size_t)(k0 + tr) * DIMN + c0 + 4);
        *(float4*)&Bs[tr][c0]     = b0;
        *(float4*)&Bs[tr][c0 + 4] = b1;
        __syncthreads();
#pragma unroll
        for (int kk = 0; kk < 16; kk++) {
            float4 a4 = *(float4*)&As[kk][r0];
            float ar[4] = {a4.x, a4.y, a4.z, a4.w};
            float4 u = *(float4*)&Bs[kk][c0];
            float4 v = *(float4*)&Bs[kk][c0 + 4];
            float br[8] = {u.x, u.y, u.z, u.w, v.x, v.y, v.z, v.w};
#pragma unroll
            for (int i = 0; i < 4; i++)
#pragma unroll
                for (int j = 0; j < 8; j++) acc[i][j] += ar[i] * br[j];
        }
        __syncthreads();
    }

    float a1v[8], a2v[8];
#pragma unroll
    for (int j = 0; j < 8; j++) {
        a1v[j] = a1[h * DIMN + c0 + j];
        a2v[j] = a2[h * DIMN + c0 + j];
    }
#pragma unroll
    for (int i = 0; i < 4; i++) {
        const int row = i0 + r0 + i;
        float s1 = 0.f, s2 = 0.f;
#pragma unroll
        for (int j = 0; j < 8; j++) { s1 += acc[i][j] * a1v[j]; s2 += acc[i][j] * a2v[j]; }
#pragma unroll
        for (int m = 8; m >= 1; m >>= 1) {
            s1 += __shfl_xor_sync(0xffffffffu, s1, m);
            s2 += __shfl_xor_sync(0xffffffffu, s2, m);
        }
        if (tc == 0) {
            const int idx = h * NN + row;
            g_E1p[idx] = __float2half(__expf(fminf(s1, 5.5f)));
            g_E1n[idx] = __float2half(__expf(ALPHA * s1));
            g_E2p[idx] = __float2half(__expf(fminf(s2, 5.5f)));
            g_E2n[idx] = __float2half(__expf(ALPHA * s2));
        }
        __half2 p0 = __floats2half2_rn(acc[i][0], acc[i][1]);
        __half2 p1 = __floats2half2_rn(acc[i][2], acc[i][3]);
        __half2 p2 = __floats2half2_rn(acc[i][4], acc[i][5]);
        __half2 p3 = __floats2half2_rn(acc[i][6], acc[i][7]);
        uint4 st = make_uint4(*(uint32_t*)&p0, *(uint32_t*)&p1,
                              *(uint32_t*)&p2, *(uint32_t*)&p3);
        *(uint4*)((char*)g_Whh + (((size_t)h * NN + row) * DIMN + c0) * 2) = st;
    }
}

// ---------------------------------------------------------------------------
// Kernel 2: attention via ldmatrix + mma.sync (fp16 in, fp32 accum).
// CTA = 128 i-rows x 1 head; 8 warps in 4x2 (row x col) layout, warp tile
// 32 rows x 64 cols.  j-loop in tiles of 64; p generated in smem (swizzled),
// Wh tile loaded [j][d] row-major; den = extra MMA vs constant ones-B.
// Double-buffered smem, one __syncthreads per tile.
// ---------------------------------------------------------------------------
#define SMA0 0
#define SMA1 16384
#define SMB0 32768
#define SMB1 49152
#define SM_TOTAL 65536

__global__ void __launch_bounds__(256, 2) k_attn_mma() {
    extern __shared__ char sm[];
    const uint32_t smb = smem_u32(sm);
    const int tid  = threadIdx.x;
    const int lane = tid & 31;
    const int wid  = tid >> 5;
    const int h  = blockIdx.y;
    const int i0 = blockIdx.x * 128;

    const int m0  = (wid & 3) * 32;   // warp row base
    const int n0w = (wid >> 2) * 64;  // warp col base

    float acc[2][8][4];
    float accd[2][4];
#pragma unroll
    for (int mi = 0; mi < 2; mi++) {
#pragma unroll
        for (int t = 0; t < 8; t++)
#pragma unroll
            for (int q = 0; q < 4; q++) acc[mi][t][q] = 0.f;
#pragma unroll
        for (int q = 0; q < 4; q++) accd[mi][q] = 0.f;
    }
    const uint32_t ONES = 0x3C003C00u;  // fp16x2 {1,1}

    // p-gen mapping: thread -> (row pr, 32-j half jh)
    const int pr = tid >> 1;
    const int jh = (tid & 1) * 32;
    const uint32_t e1p_s = ((const unsigned short*)g_E1p)[h * NN + i0 + pr];
    const uint32_t e1n_s = ((const unsigned short*)g_E1n)[h * NN + i0 + pr];
    const uint32_t e1p2 = e1p_s | (e1p_s << 16);
    const uint32_t e1n2 = e1n_s | (e1n_s << 16);
    const uint4* mkrow = (const uint4*)(g_maskx + (size_t)(i0 + pr) * (NN / 2));

    // Wh-load mapping: thread -> (row wrow, 4 chunks)
    const int wrow = tid >> 2;
    const int wcb  = (tid & 3) * 4;

    const uint32_t aOff[2] = {smb + SMA0, smb + SMA1};
    const uint32_t bOff[2] = {smb + SMB0, smb + SMB1};
    char* aPtr[2] = {sm + SMA0, sm + SMA1};
    char* bPtr[2] = {sm + SMB0, sm + SMB1};

    for (int t = 0; t < 64; t++) {
        const int s = t & 1;
        const int j0 = t * 64;

        // ---- load Wh tile [64 j][128 d], swizzled 16B chunks ----
        {
            const uint4* src = (const uint4*)((const char*)g_Whh +
                               ((size_t)h * NN + j0 + wrow) * (DIMN * 2));
            char* dstBase = bPtr[s] + wrow * 256;
#pragma unroll
            for (int c = 0; c < 4; c++) {
                int chunk = wcb + c;
                *(uint4*)(dstBase + ((chunk ^ ((wrow & 7) << 1)) << 4)) = src[chunk];
            }
        }
        // ---- generate p tile [128 i][64 j], swizzled ----
        {
            const uint4* mk4 = mkrow + ((j0 + jh) >> 3);
            const uint4* ep4 = (const uint4*)((const char*)g_E2p + ((size_t)h * NN + j0 + jh) * 2);
            const uint4* en4 = (const uint4*)((const char*)g_E2n + ((size_t)h * NN + j0 + jh) * 2);
            char* dstBase = aPtr[s] + pr * 128;
#pragma unroll
            for (int c = 0; c < 4; c++) {
                uint4 mk = mk4[c], ap = ep4[c], an = en4[c], o;
                o.x = h2mulmax(e1p2, e1n2, ap.x, an.x, mk.x);
                o.y = h2mulmax(e1p2, e1n2, ap.y, an.y, mk.y);
                o.z = h2mulmax(e1p2, e1n2, ap.z, an.z, mk.z);
                o.w = h2mulmax(e1p2, e1n2, ap.w, an.w, mk.w);
                int chunk = (tid & 1) * 4 + c;
                *(uint4*)(dstBase + ((chunk ^ (pr & 7)) << 4)) = o;
            }
        }
        __syncthreads();

        // ---- MMA over this tile: k = 64 in 4 steps of 16 ----
#pragma unroll
        for (int k0 = 0; k0 < 64; k0 += 16) {
            uint32_t a[2][4];
#pragma unroll
            for (int mi = 0; mi < 2; mi++) {
                int rowA = m0 + mi * 16 + (lane & 15);
                int chA  = (k0 >> 3) + (lane >> 4);
                ldsm4(a[mi][0], a[mi][1], a[mi][2], a[mi][3],
                      aOff[s] + rowA * 128 + ((chA ^ (rowA & 7)) << 4));
            }
            uint32_t b[4][4];
#pragma unroll
            for (int nt = 0; nt < 4; nt++) {
                int rowB = k0 + (lane & 15);
                int chB  = (n0w >> 3) + nt * 2 + (lane >> 4);
                ldsm4t(b[nt][0], b[nt][1], b[nt][2], b[nt][3],
                       bOff[s] + rowB * 256 + ((chB ^ ((rowB & 7) << 1)) << 4));
            }
#pragma unroll
            for (int mi = 0; mi < 2; mi++) {
#pragma unroll
                for (int nt = 0; nt < 4; nt++) {
                    mma16816(acc[mi][nt * 2 + 0], a[mi], b[nt][0], b[nt][1]);
                    mma16816(acc[mi][nt * 2 + 1], a[mi], b[nt][2], b[nt][3]);
                }
                mma16816(accd[mi], a[mi], ONES, ONES);
            }
        }
    }

    // ---- epilogue: normalize, ELU, store fp32 ----
#pragma unroll
    for (int mi = 0; mi < 2; mi++) {
        const float inv1 = 1.0f / accd[mi][0];
        const float inv2 = 1.0f / accd[mi][2];
        const int r1 = i0 + m0 + mi * 16 + (lane >> 2);
        float* d1 = g_att + ((size_t)h * NN + r1) * DIMN + n0w + 2 * (lane & 3);
        float* d2 = d1 + 8 * DIMN;
#pragma unroll
        for (int nt = 0; nt < 8; nt++) {
            float v0 = acc[mi][nt][0] * inv1;
            float v1 = acc[mi][nt][1] * inv1;
            float v2 = acc[mi][nt][2] * inv2;
            float v3 = acc[mi][nt][3] * inv2;
            v0 = v0 > 0.f ? v0 : expm1f(v0);
            v1 = v1 > 0.f ? v1 : expm1f(v1);
            v2 = v2 > 0.f ? v2 : expm1f(v2);
            v3 = v3 > 0.f ? v3 : expm1f(v3);
            *(float2*)(d1 + nt * 8) = make_float2(v0, v1);
            *(float2*)(d2 + nt * 8) = make_float2(v2, v3);
        }
    }
}

// ---------------------------------------------------------------------------
// Kernel 3: x = elu(cat @ W1 + b1); out = layernorm(nodes + x)
// ---------------------------------------------------------------------------
__global__ __launch_bounds__(256) void k_out(const float* __restrict__ nodes,
                                             const float* __restrict__ W1,
                                             const float* __restrict__ b1,
                                             const float* __restrict__ gamma,
                                             const float* __restrict__ beta,
                                             float* __restrict__ out) {
    const int i0 = blockIdx.x * 64;
    __shared__ float As[16][64];
    __shared__ float Bs[16][128];

    const int tid = threadIdx.x;
    const int tr = tid >> 4, tc = tid & 15;
    const int r0 = tr * 4, c0 = tc * 8;
    const int lr = tid >> 2;
    const int kq = (tid & 3) * 4;

    float acc[4][8];
#pragma unroll
    for (int i = 0; i < 4; i++)
#pragma unroll
        for (int j = 0; j < 8; j++) acc[i][j] = 0.f;

    for (int k0 = 0; k0 < NH * DIMN; k0 += 16) {
        const int hh = k0 >> 7;
        const int db = k0 & 127;
        float4 av = *(const float4*)(g_att + ((size_t)hh * NN + i0 + lr) * DIMN + db + kq);
        As[kq + 0][lr] = av.x; As[kq + 1][lr] = av.y;
        As[kq + 2][lr] = av.z; As[kq + 3][lr] = av.w;
        float4 b0 = *(const float4*)(W1 + (size_t)(k0 + tr) * DIMN + c0);
        float4 b4 = *(const float4*)(W1 + (size_t)(k0 + tr) * DIMN + c0 + 4);
        *(float4*)&Bs[tr][c0]     = b0;
        *(float4*)&Bs[tr][c0 + 4] = b4;
        __syncthreads();
#pragma unroll
        for (int kk = 0; kk < 16; kk++) {
            float4 a4 = *(float4*)&As[kk][r0];
            float ar[4] = {a4.x, a4.y, a4.z, a4.w};
            float4 u = *(float4*)&Bs[kk][c0];
            float4 v = *(float4*)&Bs[kk][c0 + 4];
            float br[8] = {u.x, u.y, u.z, u.w, v.x, v.y, v.z, v.w};
#pragma unroll
            for (int i = 0; i < 4; i++)
#pragma unroll
                for (int j = 0; j < 8; j++) acc[i][j] += ar[i] * br[j];
        }
        __syncthreads();
    }

    float bb[8], gg[8], be[8];
#pragma unroll
    for (int j = 0; j < 8; j++) {
        bb[j] = b1[c0 + j]; gg[j] = gamma[c0 + j]; be[j] = beta[c0 + j];
    }

#pragma unroll
    for (int i = 0; i < 4; i++) {
        const int row = i0 + r0 + i;
        float t[8];
        float s = 0.f;
#pragma unroll
        for (int j = 0; j < 8; j++) {
            float v = acc[i][j] + bb[j];
            v = v > 0.f ? v : expm1f(v);
            t[j] = nodes[(size_t)row * DIMN + c0 + j] + v;
            s += t[j];
        }
#pragma unroll
        for (int m = 8; m >= 1; m >>= 1) s += __shfl_xor_sync(0xffffffffu, s, m);
        const float mu = s * (1.0f / 128.0f);
        float q = 0.f;
#pragma unroll
        for (int j = 0; j < 8; j++) { float d = t[j] - mu; q += d * d; }
#pragma unroll
        for (int m = 8; m >= 1; m >>= 1) q += __shfl_xor_sync(0xffffffffu, q, m);
        const float rs = rsqrtf(q * (1.0f / 128.0f) + 1e-5f);
        float o[8];
#pragma unroll
        for (int j = 0; j < 8; j++) o[j] = (t[j] - mu) * rs * gg[j] + be[j];
        float* dst = out + (size_t)row * DIMN + c0;
        *(float4*)dst       = make_float4(o[0], o[1], o[2], o[3]);
        *(float4*)(dst + 4) = make_float4(o[4], o[5], o[6], o[7]);
    }
}

// ---------------------------------------------------------------------------
extern "C" void kernel_launch(void* const* d_in, const int* in_sizes, int n_in,
                              void* d_out, int out_size) {
    const float* nodes = (const float*)d_in[0];
    const int*   adj   = (const int*)d_in[1];
    const float* W     = (const float*)d_in[2];
    const float* a1    = (const float*)d_in[3];
    const float* a2    = (const float*)d_in[4];
    const float* W1    = (const float*)d_in[5];
    const float* b1    = (const float*)d_in[6];
    const float* gamma = (const float*)d_in[7];
    const float* beta  = (const float*)d_in[8];
    float* out = (float*)d_out;

    cudaFuncSetAttribute(k_attn_mma, cudaFuncAttributeMaxDynamicSharedMemorySize, SM_TOTAL);

    k_mask<<<(NN * (NN / 2)) / 256, 256>>>(adj);
    dim3 gridWh(NN / 64, NH);
    k_wh<<<gridWh, 256>>>(nodes, W, a1, a2);
    dim3 gridAttn(NN / 128, NH);
    k_attn_mma<<<gridAttn, 256, SM_TOTAL>>>();
    k_out<<<NN / 64, 256>>>(nodes, W1, b1, gamma, beta, out);
}

// round 11
// speedup vs baseline: 3.7170x; 1.3192x over previous
#include <cuda_runtime.h>
#include <cuda_fp16.h>
#include <cstdint>

#define NN 4096
#define DIMN 128
#define NH 8
#define ALPHA 0.2f

// ---------------- device scratch (no allocation allowed) -------------------
__device__ __half g_Whh[(size_t)NH * NN * DIMN];          // [h][n][d] fp16
__device__ float g_part[(size_t)NH * NN * DIMN];          // per-head GEMM partials
__device__ __half g_E1p[NH * NN];  // exp(min(f1,5.5))
__device__ __half g_E1n[NH * NN];  // exp(0.2*f1)
__device__ __half g_E2p[NH * NN];  // exp(min(f2,5.5))
__device__ __half g_E2n[NH * NN];  // exp(0.2*f2)
__device__ unsigned int g_maskx[(size_t)NN * (NN / 2)];   // 16-bit AND masks, packed x2

// ---------------- helpers ---------------------------------------------------
__device__ __forceinline__ uint32_t smem_u32(const void* p) {
    uint32_t a;
    asm("{ .reg .u64 t; cvta.to.shared.u64 t, %1; cvt.u32.u64 %0, t; }" : "=r"(a) : "l"(p));
    return a;
}
__device__ __forceinline__ void ldsm4(uint32_t& r0, uint32_t& r1, uint32_t& r2,
                                      uint32_t& r3, uint32_t addr) {
    asm volatile("ldmatrix.sync.aligned.m8n8.x4.shared.b16 {%0,%1,%2,%3}, [%4];"
                 : "=r"(r0), "=r"(r1), "=r"(r2), "=r"(r3) : "r"(addr));
}
__device__ __forceinline__ void ldsm4t(uint32_t& r0, uint32_t& r1, uint32_t& r2,
                                       uint32_t& r3, uint32_t addr) {
    asm volatile("ldmatrix.sync.aligned.m8n8.x4.trans.shared.b16 {%0,%1,%2,%3}, [%4];"
                 : "=r"(r0), "=r"(r1), "=r"(r2), "=r"(r3) : "r"(addr));
}
__device__ __forceinline__ void mma16816(float* c, const uint32_t* a,
                                         uint32_t b0, uint32_t b1) {
    asm volatile(
        "mma.sync.aligned.m16n8k16.row.col.f32.f16.f16.f32 "
        "{%0,%1,%2,%3}, {%4,%5,%6,%7}, {%8,%9}, {%0,%1,%2,%3};"
        : "+f"(c[0]), "+f"(c[1]), "+f"(c[2]), "+f"(c[3])
        : "r"(a[0]), "r"(a[1]), "r"(a[2]), "r"(a[3]), "r"(b0), "r"(b1));
}
__device__ __forceinline__ uint32_t h2mulmax(uint32_t e1p, uint32_t e1n,
                                             uint32_t e2p, uint32_t e2n,
                                             uint32_t msk) {
    __half2 u = __hmul2(*(__half2*)&e1p, *(__half2*)&e2p);
    __half2 v = __hmul2(*(__half2*)&e1n, *(__half2*)&e2n);
    __half2 m = __hmax2(u, v);
    return (*(uint32_t*)&m) & msk;
}

// ---------------------------------------------------------------------------
// adj -> packed 16-bit AND masks
// ---------------------------------------------------------------------------
__global__ __launch_bounds__(256) void k_mask(const int* __restrict__ adj) {
    size_t idx = (size_t)blockIdx.x * 256 + threadIdx.x;
    int2 a = ((const int2*)adj)[idx];
    g_maskx[idx] = (a.x > 0 ? 0x0000FFFFu : 0u) | (a.y > 0 ? 0xFFFF0000u : 0u);
}

// ---------------------------------------------------------------------------
// Kernel 1: Wh (fp16) + fused exp tables from f1/f2
// ---------------------------------------------------------------------------
__global__ __launch_bounds__(256) void k_wh(const float* __restrict__ nodes,
                                            const float* __restrict__ W,
                                            const float* __restrict__ a1,
                                            const float* __restrict__ a2) {
    const int i0 = blockIdx.x * 64;
    const int h  = blockIdx.y;
    __shared__ float As[16][64];
    __shared__ float Bs[16][128];

    const int tid = threadIdx.x;
    const int tr = tid >> 4, tc = tid & 15;
    const int r0 = tr * 4, c0 = tc * 8;

    float acc[4][8];
#pragma unroll
    for (int i = 0; i < 4; i++)
#pragma unroll
        for (int j = 0; j < 8; j++) acc[i][j] = 0.f;

    const float* Wp = W + (size_t)h * DIMN * DIMN;
    const int lr = tid >> 2;
    const int kq = (tid & 3) * 4;

    for (int k0 = 0; k0 < DIMN; k0 += 16) {
        float4 av = *(const float4*)(nodes + (size_t)(i0 + lr) * DIMN + k0 + kq);
        As[kq + 0][lr] = av.x; As[kq + 1][lr] = av.y;
        As[kq + 2][lr] = av.z; As[kq + 3][lr] = av.w;
        float4 b0 = *(const float4*)(Wp + (size_t)(k0 + tr) * DIMN + c0);
        float4 b1 = *(const float4*)(Wp + (size_t)(k0 + tr) * DIMN + c0 + 4);
        *(float4*)&Bs[tr][c0]     = b0;
        *(float4*)&Bs[tr][c0 + 4] = b1;
        __syncthreads();
#pragma unroll
        for (int kk = 0; kk < 16; kk++) {
            float4 a4 = *(float4*)&As[kk][r0];
            float ar[4] = {a4.x, a4.y, a4.z, a4.w};
            float4 u = *(float4*)&Bs[kk][c0];
            float4 v = *(float4*)&Bs[kk][c0 + 4];
            float br[8] = {u.x, u.y, u.z, u.w, v.x, v.y, v.z, v.w};
#pragma unroll
            for (int i = 0; i < 4; i++)
#pragma unroll
                for (int j = 0; j < 8; j++) acc[i][j] += ar[i] * br[j];
        }
        __syncthreads();
    }

    float a1v[8], a2v[8];
#pragma unroll
    for (int j = 0; j < 8; j++) {
        a1v[j] = a1[h * DIMN + c0 + j];
        a2v[j] = a2[h * DIMN + c0 + j];
    }
#pragma unroll
    for (int i = 0; i < 4; i++) {
        const int row = i0 + r0 + i;
        float s1 = 0.f, s2 = 0.f;
#pragma unroll
        for (int j = 0; j < 8; j++) { s1 += acc[i][j] * a1v[j]; s2 += acc[i][j] * a2v[j]; }
#pragma unroll
        for (int m = 8; m >= 1; m >>= 1) {
            s1 += __shfl_xor_sync(0xffffffffu, s1, m);
            s2 += __shfl_xor_sync(0xffffffffu, s2, m);
        }
        if (tc == 0) {
            const int idx = h * NN + row;
            g_E1p[idx] = __float2half(__expf(fminf(s1, 5.5f)));
            g_E1n[idx] = __float2half(__expf(ALPHA * s1));
            g_E2p[idx] = __float2half(__expf(fminf(s2, 5.5f)));
            g_E2n[idx] = __float2half(__expf(ALPHA * s2));
        }
        __half2 p0 = __floats2half2_rn(acc[i][0], acc[i][1]);
        __half2 p1 = __floats2half2_rn(acc[i][2], acc[i][3]);
        __half2 p2 = __floats2half2_rn(acc[i][4], acc[i][5]);
        __half2 p3 = __floats2half2_rn(acc[i][6], acc[i][7]);
        uint4 st = make_uint4(*(uint32_t*)&p0, *(uint32_t*)&p1,
                              *(uint32_t*)&p2, *(uint32_t*)&p3);
        *(uint4*)((char*)g_Whh + (((size_t)h * NN + row) * DIMN + c0) * 2) = st;
    }
}

// ---------------------------------------------------------------------------
// Kernel 2: attention + fused per-head linear1 partial GEMM.
// Phase 1 (as before): flash HMMA over j-tiles -> elu(att@Wh) fragments.
// Phase 2: elu tile (fp16) @ W1[h-slice] (fp16) -> g_part[h] fp32.
// ---------------------------------------------------------------------------
#define SMA0 0
#define SMA1 16384
#define SMB0 32768
#define SMB1 49152
#define SM_TOTAL 65536

__global__ void __launch_bounds__(256, 2) k_attn_mma(const float* __restrict__ W1) {
    extern __shared__ char sm[];
    const uint32_t smb = smem_u32(sm);
    const int tid  = threadIdx.x;
    const int lane = tid & 31;
    const int wid  = tid >> 5;
    const int h  = blockIdx.y;
    const int i0 = blockIdx.x * 128;

    const int m0  = (wid & 3) * 32;   // warp row base
    const int n0w = (wid >> 2) * 64;  // warp col base

    float acc[2][8][4];
    float accd[2][4];
#pragma unroll
    for (int mi = 0; mi < 2; mi++) {
#pragma unroll
        for (int t = 0; t < 8; t++)
#pragma unroll
            for (int q = 0; q < 4; q++) acc[mi][t][q] = 0.f;
#pragma unroll
        for (int q = 0; q < 4; q++) accd[mi][q] = 0.f;
    }
    const uint32_t ONES = 0x3C003C00u;  // fp16x2 {1,1}

    const int pr = tid >> 1;
    const int jh = (tid & 1) * 32;
    const uint32_t e1p_s = ((const unsigned short*)g_E1p)[h * NN + i0 + pr];
    const uint32_t e1n_s = ((const unsigned short*)g_E1n)[h * NN + i0 + pr];
    const uint32_t e1p2 = e1p_s | (e1p_s << 16);
    const uint32_t e1n2 = e1n_s | (e1n_s << 16);
    const uint4* mkrow = (const uint4*)(g_maskx + (size_t)(i0 + pr) * (NN / 2));

    const int wrow = tid >> 2;
    const int wcb  = (tid & 3) * 4;

    const uint32_t aOff[2] = {smb + SMA0, smb + SMA1};
    const uint32_t bOff[2] = {smb + SMB0, smb + SMB1};
    char* aPtr[2] = {sm + SMA0, sm + SMA1};
    char* bPtr[2] = {sm + SMB0, sm + SMB1};

    for (int t = 0; t < 64; t++) {
        const int s = t & 1;
        const int j0 = t * 64;

        // ---- load Wh tile [64 j][128 d], swizzled 16B chunks ----
        {
            const uint4* src = (const uint4*)((const char*)g_Whh +
                               ((size_t)h * NN + j0 + wrow) * (DIMN * 2));
            char* dstBase = bPtr[s] + wrow * 256;
#pragma unroll
            for (int c = 0; c < 4; c++) {
                int chunk = wcb + c;
                *(uint4*)(dstBase + ((chunk ^ ((wrow & 7) << 1)) << 4)) = src[chunk];
            }
        }
        // ---- generate p tile [128 i][64 j], swizzled ----
        {
            const uint4* mk4 = mkrow + ((j0 + jh) >> 3);
            const uint4* ep4 = (const uint4*)((const char*)g_E2p + ((size_t)h * NN + j0 + jh) * 2);
            const uint4* en4 = (const uint4*)((const char*)g_E2n + ((size_t)h * NN + j0 + jh) * 2);
            char* dstBase = aPtr[s] + pr * 128;
#pragma unroll
            for (int c = 0; c < 4; c++) {
                uint4 mk = mk4[c], ap = ep4[c], an = en4[c], o;
                o.x = h2mulmax(e1p2, e1n2, ap.x, an.x, mk.x);
                o.y = h2mulmax(e1p2, e1n2, ap.y, an.y, mk.y);
                o.z = h2mulmax(e1p2, e1n2, ap.z, an.z, mk.z);
                o.w = h2mulmax(e1p2, e1n2, ap.w, an.w, mk.w);
                int chunk = (tid & 1) * 4 + c;
                *(uint4*)(dstBase + ((chunk ^ (pr & 7)) << 4)) = o;
            }
        }
        __syncthreads();

        // ---- MMA over this tile: k = 64 in 4 steps of 16 ----
#pragma unroll
        for (int k0 = 0; k0 < 64; k0 += 16) {
            uint32_t a[2][4];
#pragma unroll
            for (int mi = 0; mi < 2; mi++) {
                int rowA = m0 + mi * 16 + (lane & 15);
                int chA  = (k0 >> 3) + (lane >> 4);
                ldsm4(a[mi][0], a[mi][1], a[mi][2], a[mi][3],
                      aOff[s] + rowA * 128 + ((chA ^ (rowA & 7)) << 4));
            }
            uint32_t b[4][4];
#pragma unroll
            for (int nt = 0; nt < 4; nt++) {
                int rowB = k0 + (lane & 15);
                int chB  = (n0w >> 3) + nt * 2 + (lane >> 4);
                ldsm4t(b[nt][0], b[nt][1], b[nt][2], b[nt][3],
                       bOff[s] + rowB * 256 + ((chB ^ ((rowB & 7) << 1)) << 4));
            }
#pragma unroll
            for (int mi = 0; mi < 2; mi++) {
#pragma unroll
                for (int nt = 0; nt < 4; nt++) {
                    mma16816(acc[mi][nt * 2 + 0], a[mi], b[nt][0], b[nt][1]);
                    mma16816(acc[mi][nt * 2 + 1], a[mi], b[nt][2], b[nt][3]);
                }
                mma16816(accd[mi], a[mi], ONES, ONES);
            }
        }
    }
    __syncthreads();  // all warps done with main-loop buffers

    // ---- Phase 2a: normalize, ELU -> fp16 smem tile [128 r][128 d] at SMA0 ----
    {
        char* eluBase = sm + SMA0;  // 128 rows x 256B = 32KB (SMA0+SMA1)
#pragma unroll
        for (int mi = 0; mi < 2; mi++) {
            const float inv1 = 1.0f / accd[mi][0];
            const float inv2 = 1.0f / accd[mi][2];
            const int r1 = m0 + mi * 16 + (lane >> 2);
            const int r2 = r1 + 8;
#pragma unroll
            for (int nt = 0; nt < 8; nt++) {
                float v0 = acc[mi][nt][0] * inv1;
                float v1 = acc[mi][nt][1] * inv1;
                float v2 = acc[mi][nt][2] * inv2;
                float v3 = acc[mi][nt][3] * inv2;
                v0 = v0 > 0.f ? v0 : expm1f(v0);
                v1 = v1 > 0.f ? v1 : expm1f(v1);
                v2 = v2 > 0.f ? v2 : expm1f(v2);
                v3 = v3 > 0.f ? v3 : expm1f(v3);
                const uint32_t off = (uint32_t)(n0w + nt * 8 + 2 * (lane & 3)) * 2;
                const uint32_t ch = off >> 4, wi = off & 15;
                __half2 hv1 = __floats2half2_rn(v0, v1);
                __half2 hv2 = __floats2half2_rn(v2, v3);
                *(__half2*)(eluBase + r1 * 256 + ((ch ^ ((r1 & 7) << 1)) << 4) + wi) = hv1;
                *(__half2*)(eluBase + r2 * 256 + ((ch ^ ((r2 & 7) << 1)) << 4) + wi) = hv2;
            }
        }
    }
    // ---- Phase 2b: W1 head-slice [128 d][128 out] fp32->fp16 smem at SMB0 ----
    {
        const int drow = tid >> 1;
        const int cb = (tid & 1) * 64;
        const float* w1p = W1 + ((size_t)(h * DIMN + drow)) * DIMN + cb;
        char* wBase = sm + SMB0;
#pragma unroll
        for (int c = 0; c < 16; c++) {
            float4 f = *(const float4*)(w1p + c * 4);
            __half2 h0 = __floats2half2_rn(f.x, f.y);
            __half2 h1 = __floats2half2_rn(f.z, f.w);
            const uint32_t off = (uint32_t)(cb + c * 4) * 2;
            const uint32_t ch = off >> 4, wi = off & 15;
            uint2 st = make_uint2(*(uint32_t*)&h0, *(uint32_t*)&h1);
            *(uint2*)(wBase + drow * 256 + ((ch ^ ((drow & 7) << 1)) << 4) + wi) = st;
        }
    }
    __syncthreads();

    // ---- Phase 2c: C2 = elu @ W1h  (128x128x128), write g_part[h] ----
    {
        float c2[2][8][4];
#pragma unroll
        for (int mi = 0; mi < 2; mi++)
#pragma unroll
            for (int t = 0; t < 8; t++)
#pragma unroll
                for (int q = 0; q < 4; q++) c2[mi][t][q] = 0.f;

        const uint32_t eluOff = smb + SMA0;
        const uint32_t wOff = smb + SMB0;
#pragma unroll
        for (int k0 = 0; k0 < 128; k0 += 16) {
            uint32_t a[2][4];
#pragma unroll
            for (int mi = 0; mi < 2; mi++) {
                int rowA = m0 + mi * 16 + (lane & 15);
                int chA  = (k0 >> 3) + (lane >> 4);
                ldsm4(a[mi][0], a[mi][1], a[mi][2], a[mi][3],
                      eluOff + rowA * 256 + ((chA ^ ((rowA & 7) << 1)) << 4));
            }
            uint32_t b[4][4];
#pragma unroll
            for (int nt = 0; nt < 4; nt++) {
                int rowB = k0 + (lane & 15);
                int chB  = (n0w >> 3) + nt * 2 + (lane >> 4);
                ldsm4t(b[nt][0], b[nt][1], b[nt][2], b[nt][3],
                       wOff + rowB * 256 + ((chB ^ ((rowB & 7) << 1)) << 4));
            }
#pragma unroll
            for (int mi = 0; mi < 2; mi++)
#pragma unroll
                for (int nt = 0; nt < 4; nt++) {
                    mma16816(c2[mi][nt * 2 + 0], a[mi], b[nt][0], b[nt][1]);
                    mma16816(c2[mi][nt * 2 + 1], a[mi], b[nt][2], b[nt][3]);
                }
        }
#pragma unroll
        for (int mi = 0; mi < 2; mi++) {
            const int r1 = i0 + m0 + mi * 16 + (lane >> 2);
            float* d1 = g_part + ((size_t)h * NN + r1) * DIMN + n0w + 2 * (lane & 3);
            float* d2 = d1 + 8 * DIMN;
#pragma unroll
            for (int nt = 0; nt < 8; nt++) {
                *(float2*)(d1 + nt * 8) = make_float2(c2[mi][nt][0], c2[mi][nt][1]);
                *(float2*)(d2 + nt * 8) = make_float2(c2[mi][nt][2], c2[mi][nt][3]);
            }
        }
    }
}

// ---------------------------------------------------------------------------
// Kernel 3: sum 8 head-partials + b1, elu, + nodes, layernorm -> out.
// One warp per row; lane holds 4 cols.
// ---------------------------------------------------------------------------
__global__ __launch_bounds__(256) void k_final(const float* __restrict__ nodes,
                                               const float* __restrict__ b1,
                                               const float* __restrict__ gamma,
                                               const float* __restrict__ beta,
                                               float* __restrict__ out) {
    const int lane = threadIdx.x & 31;
    const int row = blockIdx.x * 8 + (threadIdx.x >> 5);
    const int c = lane * 4;

    float4 s = make_float4(0.f, 0.f, 0.f, 0.f);
#pragma unroll
    for (int h = 0; h < NH; h++) {
        float4 p = *(const float4*)(g_part + ((size_t)h * NN + row) * DIMN + c);
        s.x += p.x; s.y += p.y; s.z += p.z; s.w += p.w;
    }
    float4 bb = *(const float4*)(b1 + c);
    float4 nd = *(const float4*)(nodes + (size_t)row * DIMN + c);

    float t[4];
    {
        float v;
        v = s.x + bb.x; v = v > 0.f ? v : expm1f(v); t[0] = nd.x + v;
        v = s.y + bb.y; v = v > 0.f ? v : expm1f(v); t[1] = nd.y + v;
        v = s.z + bb.z; v = v > 0.f ? v : expm1f(v); t[2] = nd.z + v;
        v = s.w + bb.w; v = v > 0.f ? v : expm1f(v); t[3] = nd.w + v;
    }
    float sum = t[0] + t[1] + t[2] + t[3];
#pragma unroll
    for (int m = 16; m >= 1; m >>= 1) sum += __shfl_xor_sync(0xffffffffu, sum, m);
    const float mu = sum * (1.0f / 128.0f);
    float q = 0.f;
#pragma unroll
    for (int j = 0; j < 4; j++) { float d = t[j] - mu; q += d * d; }
#pragma unroll
    for (int m = 16; m >= 1; m >>= 1) q += __shfl_xor_sync(0xffffffffu, q, m);
    const float rs = rsqrtf(q * (1.0f / 128.0f) + 1e-5f);

    float4 gg = *(const float4*)(gamma + c);
    float4 be = *(const float4*)(beta + c);
    float4 o;
    o.x = (t[0] - mu) * rs * gg.x + be.x;
    o.y = (t[1] - mu) * rs * gg.y + be.y;
    o.z = (t[2] - mu) * rs * gg.z + be.z;
    o.w = (t[3] - mu) * rs * gg.w + be.w;
    *(float4*)(out + (size_t)row * DIMN + c) = o;
}

// ---------------------------------------------------------------------------
extern "C" void kernel_launch(void* const* d_in, const int* in_sizes, int n_in,
                              void* d_out, int out_size) {
    const float* nodes = (const float*)d_in[0];
    const int*   adj   = (const int*)d_in[1];
    const float* W     = (const float*)d_in[2];
    const float* a1    = (const float*)d_in[3];
    const float* a2    = (const float*)d_in[4];
    const float* W1    = (const float*)d_in[5];
    const float* b1    = (const float*)d_in[6];
    const float* gamma = (const float*)d_in[7];
    const float* beta  = (const float*)d_in[8];
    float* out = (float*)d_out;

    cudaFuncSetAttribute(k_attn_mma, cudaFuncAttributeMaxDynamicSharedMemorySize, SM_TOTAL);

    k_mask<<<(NN * (NN / 2)) / 256, 256>>>(adj);
    dim3 gridWh(NN / 64, NH);
    k_wh<<<gridWh, 256>>>(nodes, W, a1, a2);
    dim3 gridAttn(NN / 128, NH);
    k_attn_mma<<<gridAttn, 256, SM_TOTAL>>>(W1);
    k_final<<<NN / 8, 256>>>(nodes, b1, gamma, beta, out);
}

// round 13
// speedup vs baseline: 4.1503x; 1.1166x over previous
#include <cuda_runtime.h>
#include <cuda_fp16.h>
#include <cstdint>

#define NN 4096
#define DIMN 128
#define NH 8
#define ALPHA 0.2f

// ---------------- device scratch (no allocation allowed) -------------------
__device__ __half g_Whh[(size_t)NH * NN * DIMN];          // [h][n][d] fp16
__device__ float g_part[(size_t)NH * NN * DIMN];          // per-head GEMM partials
__device__ __half g_E1p[NH * NN];  // exp(min(f1,5.5))
__device__ __half g_E1n[NH * NN];  // exp(0.2*f1)
__device__ __half g_E2p[NH * NN];  // exp(min(f2,5.5))
__device__ __half g_E2n[NH * NN];  // exp(0.2*f2)
__device__ unsigned int g_maskx[(size_t)NN * (NN / 2)];   // 16-bit AND masks, packed x2

// ---------------- helpers ---------------------------------------------------
__device__ __forceinline__ uint32_t smem_u32(const void* p) {
    uint32_t a;
    asm("{ .reg .u64 t; cvta.to.shared.u64 t, %1; cvt.u32.u64 %0, t; }" : "=r"(a) : "l"(p));
    return a;
}
__device__ __forceinline__ void ldsm4(uint32_t& r0, uint32_t& r1, uint32_t& r2,
                                      uint32_t& r3, uint32_t addr) {
    asm volatile("ldmatrix.sync.aligned.m8n8.x4.shared.b16 {%0,%1,%2,%3}, [%4];"
                 : "=r"(r0), "=r"(r1), "=r"(r2), "=r"(r3) : "r"(addr));
}
__device__ __forceinline__ void ldsm4t(uint32_t& r0, uint32_t& r1, uint32_t& r2,
                                       uint32_t& r3, uint32_t addr) {
    asm volatile("ldmatrix.sync.aligned.m8n8.x4.trans.shared.b16 {%0,%1,%2,%3}, [%4];"
                 : "=r"(r0), "=r"(r1), "=r"(r2), "=r"(r3) : "r"(addr));
}
__device__ __forceinline__ void mma16816(float* c, const uint32_t* a,
                                         uint32_t b0, uint32_t b1) {
    asm volatile(
        "mma.sync.aligned.m16n8k16.row.col.f32.f16.f16.f32 "
        "{%0,%1,%2,%3}, {%4,%5,%6,%7}, {%8,%9}, {%0,%1,%2,%3};"
        : "+f"(c[0]), "+f"(c[1]), "+f"(c[2]), "+f"(c[3])
        : "r"(a[0]), "r"(a[1]), "r"(a[2]), "r"(a[3]), "r"(b0), "r"(b1));
}
__device__ __forceinline__ uint32_t h2mulmax(uint32_t e1p, uint32_t e1n,
                                             uint32_t e2p, uint32_t e2n,
                                             uint32_t msk) {
    __half2 u = __hmul2(*(__half2*)&e1p, *(__half2*)&e2p);
    __half2 v = __hmul2(*(__half2*)&e1n, *(__half2*)&e2n);
    __half2 m = __hmax2(u, v);
    return (*(uint32_t*)&m) & msk;
}

// ---------------------------------------------------------------------------
// adj -> packed 16-bit AND masks
// ---------------------------------------------------------------------------
__global__ __launch_bounds__(256) void k_mask(const int* __restrict__ adj) {
    size_t idx = (size_t)blockIdx.x * 256 + threadIdx.x;
    int2 a = ((const int2*)adj)[idx];
    g_maskx[idx] = (a.x > 0 ? 0x0000FFFFu : 0u) | (a.y > 0 ? 0xFFFF0000u : 0u);
}

// ---------------------------------------------------------------------------
// Kernel 1 (HMMA): Wh[h] = nodes @ W[h] in fp16 tensor cores.
// CTA = (128 i-rows, head h).  A = nodes fp16 smem, B = W[h] fp16 smem,
// K = 128 in 8 steps.  Epilogue: Wh -> gmem fp16 straight from fragments;
// f1/f2 via fragment dot with a1/a2 (shfl + smem combine) -> exp tables.
// ---------------------------------------------------------------------------
#define WH_SMB 32768
#define WH_SMTOT 65536

__global__ void __launch_bounds__(256, 2) k_wh_mma(const float* __restrict__ nodes,
                                                   const float* __restrict__ W,
                                                   const float* __restrict__ a1,
                                                   const float* __restrict__ a2) {
    extern __shared__ char sm[];
    const uint32_t smb = smem_u32(sm);
    const int tid  = threadIdx.x;
    const int lane = tid & 31;
    const int wid  = tid >> 5;
    const int h  = blockIdx.y;
    const int i0 = blockIdx.x * 128;

    // ---- load A (nodes) and B (W[h]) as fp16, swizzled 256B rows ----
    {
        const int drow = tid >> 1;
        const int cb = (tid & 1) * 64;
        const float* ap = nodes + (size_t)(i0 + drow) * DIMN + cb;
        const float* bp = W + ((size_t)h * DIMN + drow) * DIMN + cb;
#pragma unroll
        for (int c = 0; c < 16; c++) {
            const uint32_t off = (uint32_t)(cb + c * 4) * 2;
            const uint32_t ch = off >> 4, wi = off & 15;
            const uint32_t sw = ((ch ^ ((drow & 7) << 1)) << 4) + wi;
            float4 fa = *(const float4*)(ap + c * 4);
            __half2 a0 = __floats2half2_rn(fa.x, fa.y);
            __half2 a1h = __floats2half2_rn(fa.z, fa.w);
            *(uint2*)(sm + drow * 256 + sw) =
                make_uint2(*(uint32_t*)&a0, *(uint32_t*)&a1h);
            float4 fb = *(const float4*)(bp + c * 4);
            __half2 b0 = __floats2half2_rn(fb.x, fb.y);
            __half2 b1h = __floats2half2_rn(fb.z, fb.w);
            *(uint2*)(sm + WH_SMB + drow * 256 + sw) =
                make_uint2(*(uint32_t*)&b0, *(uint32_t*)&b1h);
        }
    }
    __syncthreads();

    // ---- MMA 128x128x128 ----
    const int m0  = (wid & 3) * 32;
    const int n0w = (wid >> 2) * 64;
    float acc[2][8][4];
#pragma unroll
    for (int mi = 0; mi < 2; mi++)
#pragma unroll
        for (int t = 0; t < 8; t++)
#pragma unroll
            for (int q = 0; q < 4; q++) acc[mi][t][q] = 0.f;

#pragma unroll
    for (int k0 = 0; k0 < 128; k0 += 16) {
        uint32_t a[2][4];
#pragma unroll
        for (int mi = 0; mi < 2; mi++) {
            int rowA = m0 + mi * 16 + (lane & 15);
            int chA  = (k0 >> 3) + (lane >> 4);
            ldsm4(a[mi][0], a[mi][1], a[mi][2], a[mi][3],
                  smb + rowA * 256 + ((chA ^ ((rowA & 7) << 1)) << 4));
        }
        uint32_t b[4][4];
#pragma unroll
        for (int nt = 0; nt < 4; nt++) {
            int rowB = k0 + (lane & 15);
            int chB  = (n0w >> 3) + nt * 2 + (lane >> 4);
            ldsm4t(b[nt][0], b[nt][1], b[nt][2], b[nt][3],
                   smb + WH_SMB + rowB * 256 + ((chB ^ ((rowB & 7) << 1)) << 4));
        }
#pragma unroll
        for (int mi = 0; mi < 2; mi++)
#pragma unroll
            for (int nt = 0; nt < 4; nt++) {
                mma16816(acc[mi][nt * 2 + 0], a[mi], b[nt][0], b[nt][1]);
                mma16816(acc[mi][nt * 2 + 1], a[mi], b[nt][2], b[nt][3]);
            }
    }
    __syncthreads();  // A/B smem now free

    // ---- Wh -> gmem fp16 straight from fragments ----
#pragma unroll
    for (int mi = 0; mi < 2; mi++) {
        const int r1 = i0 + m0 + mi * 16 + (lane >> 2);
        __half* d1 = g_Whh + ((size_t)h * NN + r1) * DIMN + n0w + 2 * (lane & 3);
        __half* d2 = d1 + 8 * DIMN;
#pragma unroll
        for (int nt = 0; nt < 8; nt++) {
            __half2 hv1 = __floats2half2_rn(acc[mi][nt][0], acc[mi][nt][1]);
            __half2 hv2 = __floats2half2_rn(acc[mi][nt][2], acc[mi][nt][3]);
            *(__half2*)(d1 + nt * 8) = hv1;
            *(__half2*)(d2 + nt * 8) = hv2;
        }
    }

    // ---- f1/f2 fragment dot with a1/a2 ----
    {
        float f1p[2][2] = {{0.f, 0.f}, {0.f, 0.f}};
        float f2p[2][2] = {{0.f, 0.f}, {0.f, 0.f}};
#pragma unroll
        for (int nt = 0; nt < 8; nt++) {
            const int c0 = h * DIMN + n0w + nt * 8 + 2 * (lane & 3);
            float w1a = a1[c0], w1b = a1[c0 + 1];
            float w2a = a2[c0], w2b = a2[c0 + 1];
#pragma unroll
            for (int mi = 0; mi < 2; mi++) {
                f1p[mi][0] += acc[mi][nt][0] * w1a + acc[mi][nt][1] * w1b;
                f1p[mi][1] += acc[mi][nt][2] * w1a + acc[mi][nt][3] * w1b;
                f2p[mi][0] += acc[mi][nt][0] * w2a + acc[mi][nt][1] * w2b;
                f2p[mi][1] += acc[mi][nt][2] * w2a + acc[mi][nt][3] * w2b;
            }
        }
#pragma unroll
        for (int m = 1; m <= 2; m <<= 1) {
#pragma unroll
            for (int mi = 0; mi < 2; mi++)
#pragma unroll
                for (int hf = 0; hf < 2; hf++) {
                    f1p[mi][hf] += __shfl_xor_sync(0xffffffffu, f1p[mi][hf], m);
                    f2p[mi][hf] += __shfl_xor_sync(0xffffffffu, f2p[mi][hf], m);
                }
        }
        // smem combine across the 2 col-warp-groups
        float* fbuf = (float*)sm;  // [grp*2 + which][128]
        if ((lane & 3) == 0) {
            const int grp = wid >> 2;
#pragma unroll
            for (int mi = 0; mi < 2; mi++)
#pragma unroll
                for (int hf = 0; hf < 2; hf++) {
                    const int r = m0 + mi * 16 + (lane >> 2) + hf * 8;
                    fbuf[(grp * 2 + 0) * 128 + r] = f1p[mi][hf];
                    fbuf[(grp * 2 + 1) * 128 + r] = f2p[mi][hf];
                }
        }
    }
    __syncthreads();
    if (tid < 128) {
        float* fbuf = (float*)sm;
        const float f1 = fbuf[0 * 128 + tid] + fbuf[2 * 128 + tid];
        const float f2 = fbuf[1 * 128 + tid] + fbuf[3 * 128 + tid];
        const int idx = h * NN + i0 + tid;
        g_E1p[idx] = __float2half(__expf(fminf(f1, 5.5f)));
        g_E1n[idx] = __float2half(__expf(ALPHA * f1));
        g_E2p[idx] = __float2half(__expf(fminf(f2, 5.5f)));
        g_E2n[idx] = __float2half(__expf(ALPHA * f2));
    }
}

// ---------------------------------------------------------------------------
// Kernel 2: attention + fused per-head linear1 partial GEMM.
// ---------------------------------------------------------------------------
#define SMA0 0
#define SMA1 16384
#define SMB0 32768
#define SMB1 49152
#define SM_TOTAL 65536

__global__ void __launch_bounds__(256, 2) k_attn_mma(const float* __restrict__ W1) {
    extern __shared__ char sm[];
    const uint32_t smb = smem_u32(sm);
    const int tid  = threadIdx.x;
    const int lane = tid & 31;
    const int wid  = tid >> 5;
    const int h  = blockIdx.y;
    const int i0 = blockIdx.x * 128;

    const int m0  = (wid & 3) * 32;   // warp row base
    const int n0w = (wid >> 2) * 64;  // warp col base

    float acc[2][8][4];
    float accd[2][4];
#pragma unroll
    for (int mi = 0; mi < 2; mi++) {
#pragma unroll
        for (int t = 0; t < 8; t++)
#pragma unroll
            for (int q = 0; q < 4; q++) acc[mi][t][q] = 0.f;
#pragma unroll
        for (int q = 0; q < 4; q++) accd[mi][q] = 0.f;
    }
    const uint32_t ONES = 0x3C003C00u;  // fp16x2 {1,1}

    const int pr = tid >> 1;
    const int jh = (tid & 1) * 32;
    const uint32_t e1p_s = ((const unsigned short*)g_E1p)[h * NN + i0 + pr];
    const uint32_t e1n_s = ((const unsigned short*)g_E1n)[h * NN + i0 + pr];
    const uint32_t e1p2 = e1p_s | (e1p_s << 16);
    const uint32_t e1n2 = e1n_s | (e1n_s << 16);
    const uint4* mkrow = (const uint4*)(g_maskx + (size_t)(i0 + pr) * (NN / 2));

    const int wrow = tid >> 2;
    const int wcb  = (tid & 3) * 4;

    const uint32_t aOff[2] = {smb + SMA0, smb + SMA1};
    const uint32_t bOff[2] = {smb + SMB0, smb + SMB1};
    char* aPtr[2] = {sm + SMA0, sm + SMA1};
    char* bPtr[2] = {sm + SMB0, sm + SMB1};

    for (int t = 0; t < 64; t++) {
        const int s = t & 1;
        const int j0 = t * 64;

        // ---- load Wh tile [64 j][128 d], swizzled 16B chunks ----
        {
            const uint4* src = (const uint4*)((const char*)g_Whh +
                               ((size_t)h * NN + j0 + wrow) * (DIMN * 2));
            char* dstBase = bPtr[s] + wrow * 256;
#pragma unroll
            for (int c = 0; c < 4; c++) {
                int chunk = wcb + c;
                *(uint4*)(dstBase + ((chunk ^ ((wrow & 7) << 1)) << 4)) = src[chunk];
            }
        }
        // ---- generate p tile [128 i][64 j], swizzled ----
        {
            const uint4* mk4 = mkrow + ((j0 + jh) >> 3);
            const uint4* ep4 = (const uint4*)((const char*)g_E2p + ((size_t)h * NN + j0 + jh) * 2);
            const uint4* en4 = (const uint4*)((const char*)g_E2n + ((size_t)h * NN + j0 + jh) * 2);
            char* dstBase = aPtr[s] + pr * 128;
#pragma unroll
            for (int c = 0; c < 4; c++) {
                uint4 mk = mk4[c], ap = ep4[c], an = en4[c], o;
                o.x = h2mulmax(e1p2, e1n2, ap.x, an.x, mk.x);
                o.y = h2mulmax(e1p2, e1n2, ap.y, an.y, mk.y);
                o.z = h2mulmax(e1p2, e1n2, ap.z, an.z, mk.z);
                o.w = h2mulmax(e1p2, e1n2, ap.w, an.w, mk.w);
                int chunk = (tid & 1) * 4 + c;
                *(uint4*)(dstBase + ((chunk ^ (pr & 7)) << 4)) = o;
            }
        }
        __syncthreads();

        // ---- MMA over this tile: k = 64 in 4 steps of 16 ----
#pragma unroll
        for (int k0 = 0; k0 < 64; k0 += 16) {
            uint32_t a[2][4];
#pragma unroll
            for (int mi = 0; mi < 2; mi++) {
                int rowA = m0 + mi * 16 + (lane & 15);
                int chA  = (k0 >> 3) + (lane >> 4);
                ldsm4(a[mi][0], a[mi][1], a[mi][2], a[mi][3],
                      aOff[s] + rowA * 128 + ((chA ^ (rowA & 7)) << 4));
            }
            uint32_t b[4][4];
#pragma unroll
            for (int nt = 0; nt < 4; nt++) {
                int rowB = k0 + (lane & 15);
                int chB  = (n0w >> 3) + nt * 2 + (lane >> 4);
                ldsm4t(b[nt][0], b[nt][1], b[nt][2], b[nt][3],
                       bOff[s] + rowB * 256 + ((chB ^ ((rowB & 7) << 1)) << 4));
            }
#pragma unroll
            for (int mi = 0; mi < 2; mi++) {
#pragma unroll
                for (int nt = 0; nt < 4; nt++) {
                    mma16816(acc[mi][nt * 2 + 0], a[mi], b[nt][0], b[nt][1]);
                    mma16816(acc[mi][nt * 2 + 1], a[mi], b[nt][2], b[nt][3]);
                }
                mma16816(accd[mi], a[mi], ONES, ONES);
            }
        }
    }
    __syncthreads();  // all warps done with main-loop buffers

    // ---- Phase 2a: normalize, ELU -> fp16 smem tile [128 r][128 d] at SMA0 ----
    {
        char* eluBase = sm + SMA0;
#pragma unroll
        for (int mi = 0; mi < 2; mi++) {
            const float inv1 = 1.0f / accd[mi][0];
            const float inv2 = 1.0f / accd[mi][2];
            const int r1 = m0 + mi * 16 + (lane >> 2);
            const int r2 = r1 + 8;
#pragma unroll
            for (int nt = 0; nt < 8; nt++) {
                float v0 = acc[mi][nt][0] * inv1;
                float v1 = acc[mi][nt][1] * inv1;
                float v2 = acc[mi][nt][2] * inv2;
                float v3 = acc[mi][nt][3] * inv2;
                v0 = v0 > 0.f ? v0 : expm1f(v0);
                v1 = v1 > 0.f ? v1 : expm1f(v1);
                v2 = v2 > 0.f ? v2 : expm1f(v2);
                v3 = v3 > 0.f ? v3 : expm1f(v3);
                const uint32_t off = (uint32_t)(n0w + nt * 8 + 2 * (lane & 3)) * 2;
                const uint32_t ch = off >> 4, wi = off & 15;
                __half2 hv1 = __floats2half2_rn(v0, v1);
                __half2 hv2 = __floats2half2_rn(v2, v3);
                *(__half2*)(eluBase + r1 * 256 + ((ch ^ ((r1 & 7) << 1)) << 4) + wi) = hv1;
                *(__half2*)(eluBase + r2 * 256 + ((ch ^ ((r2 & 7) << 1)) << 4) + wi) = hv2;
            }
        }
    }
    // ---- Phase 2b: W1 head-slice [128 d][128 out] fp32->fp16 smem at SMB0 ----
    {
        const int drow = tid >> 1;
        const int cb = (tid & 1) * 64;
        const float* w1p = W1 + ((size_t)(h * DIMN + drow)) * DIMN + cb;
        char* wBase = sm + SMB0;
#pragma unroll
        for (int c = 0; c < 16; c++) {
            float4 f = *(const float4*)(w1p + c * 4);
            __half2 h0 = __floats2half2_rn(f.x, f.y);
            __half2 h1 = __floats2half2_rn(f.z, f.w);
            const uint32_t off = (uint32_t)(cb + c * 4) * 2;
            const uint32_t ch = off >> 4, wi = off & 15;
            uint2 st = make_uint2(*(uint32_t*)&h0, *(uint32_t*)&h1);
            *(uint2*)(wBase + drow * 256 + ((ch ^ ((drow & 7) << 1)) << 4) + wi) = st;
        }
    }
    __syncthreads();

    // ---- Phase 2c: C2 = elu @ W1h  (128x128x128), write g_part[h] ----
    {
        float c2[2][8][4];
#pragma unroll
        for (int mi = 0; mi < 2; mi++)
#pragma unroll
            for (int t = 0; t < 8; t++)
#pragma unroll
                for (int q = 0; q < 4; q++) c2[mi][t][q] = 0.f;

        const uint32_t eluOff = smb + SMA0;
        const uint32_t wOff = smb + SMB0;
#pragma unroll
        for (int k0 = 0; k0 < 128; k0 += 16) {
            uint32_t a[2][4];
#pragma unroll
            for (int mi = 0; mi < 2; mi++) {
                int rowA = m0 + mi * 16 + (lane & 15);
                int chA  = (k0 >> 3) + (lane >> 4);
                ldsm4(a[mi][0], a[mi][1], a[mi][2], a[mi][3],
                      eluOff + rowA * 256 + ((chA ^ ((rowA & 7) << 1)) << 4));
            }
            uint32_t b[4][4];
#pragma unroll
            for (int nt = 0; nt < 4; nt++) {
                int rowB = k0 + (lane & 15);
                int chB  = (n0w >> 3) + nt * 2 + (lane >> 4);
                ldsm4t(b[nt][0], b[nt][1], b[nt][2], b[nt][3],
                       wOff + rowB * 256 + ((chB ^ ((rowB & 7) << 1)) << 4));
            }
#pragma unroll
            for (int mi = 0; mi < 2; mi++)
#pragma unroll
                for (int nt = 0; nt < 4; nt++) {
                    mma16816(c2[mi][nt * 2 + 0], a[mi], b[nt][0], b[nt][1]);
                    mma16816(c2[mi][nt * 2 + 1], a[mi], b[nt][2], b[nt][3]);
                }
        }
#pragma unroll
        for (int mi = 0; mi < 2; mi++) {
            const int r1 = i0 + m0 + mi * 16 + (lane >> 2);
            float* d1 = g_part + ((size_t)h * NN + r1) * DIMN + n0w + 2 * (lane & 3);
            float* d2 = d1 + 8 * DIMN;
#pragma unroll
            for (int nt = 0; nt < 8; nt++) {
                *(float2*)(d1 + nt * 8) = make_float2(c2[mi][nt][0], c2[mi][nt][1]);
                *(float2*)(d2 + nt * 8) = make_float2(c2[mi][nt][2], c2[mi][nt][3]);
            }
        }
    }
}

// ---------------------------------------------------------------------------
// Kernel 3: sum 8 head-partials + b1, elu, + nodes, layernorm -> out.
// ---------------------------------------------------------------------------
__global__ __launch_bounds__(256) void k_final(const float* __restrict__ nodes,
                                               const float* __restrict__ b1,
                                               const float* __restrict__ gamma,
                                               const float* __restrict__ beta,
                                               float* __restrict__ out) {
    const int lane = threadIdx.x & 31;
    const int row = blockIdx.x * 8 + (threadIdx.x >> 5);
    const int c = lane * 4;

    float4 s = make_float4(0.f, 0.f, 0.f, 0.f);
#pragma unroll
    for (int h = 0; h < NH; h++) {
        float4 p = *(const float4*)(g_part + ((size_t)h * NN + row) * DIMN + c);
        s.x += p.x; s.y += p.y; s.z += p.z; s.w += p.w;
    }
    float4 bb = *(const float4*)(b1 + c);
    float4 nd = *(const float4*)(nodes + (size_t)row * DIMN + c);

    float t[4];
    {
        float v;
        v = s.x + bb.x; v = v > 0.f ? v : expm1f(v); t[0] = nd.x + v;
        v = s.y + bb.y; v = v > 0.f ? v : expm1f(v); t[1] = nd.y + v;
        v = s.z + bb.z; v = v > 0.f ? v : expm1f(v); t[2] = nd.z + v;
        v = s.w + bb.w; v = v > 0.f ? v : expm1f(v); t[3] = nd.w + v;
    }
    float sum = t[0] + t[1] + t[2] + t[3];
#pragma unroll
    for (int m = 16; m >= 1; m >>= 1) sum += __shfl_xor_sync(0xffffffffu, sum, m);
    const float mu = sum * (1.0f / 128.0f);
    float q = 0.f;
#pragma unroll
    for (int j = 0; j < 4; j++) { float d = t[j] - mu; q += d * d; }
#pragma unroll
    for (int m = 16; m >= 1; m >>= 1) q += __shfl_xor_sync(0xffffffffu, q, m);
    const float rs = rsqrtf(q * (1.0f / 128.0f) + 1e-5f);

    float4 gg = *(const float4*)(gamma + c);
    float4 be = *(const float4*)(beta + c);
    float4 o;
    o.x = (t[0] - mu) * rs * gg.x + be.x;
    o.y = (t[1] - mu) * rs * gg.y + be.y;
    o.z = (t[2] - mu) * rs * gg.z + be.z;
    o.w = (t[3] - mu) * rs * gg.w + be.w;
    *(float4*)(out + (size_t)row * DIMN + c) = o;
}

// ---------------------------------------------------------------------------
extern "C" void kernel_launch(void* const* d_in, const int* in_sizes, int n_in,
                              void* d_out, int out_size) {
    const float* nodes = (const float*)d_in[0];
    const int*   adj   = (const int*)d_in[1];
    const float* W     = (const float*)d_in[2];
    const float* a1    = (const float*)d_in[3];
    const float* a2    = (const float*)d_in[4];
    const float* W1    = (const float*)d_in[5];
    const float* b1    = (const float*)d_in[6];
    const float* gamma = (const float*)d_in[7];
    const float* beta  = (const float*)d_in[8];
    float* out = (float*)d_out;

    cudaFuncSetAttribute(k_attn_mma, cudaFuncAttributeMaxDynamicSharedMemorySize, SM_TOTAL);
    cudaFuncSetAttribute(k_wh_mma, cudaFuncAttributeMaxDynamicSharedMemorySize, WH_SMTOT);

    k_mask<<<(NN * (NN / 2)) / 256, 256>>>(adj);
    dim3 gridWh(NN / 128, NH);
    k_wh_mma<<<gridWh, 256, WH_SMTOT>>>(nodes, W, a1, a2);
    dim3 gridAttn(NN / 128, NH);
    k_attn_mma<<<gridAttn, 256, SM_TOTAL>>>(W1);
    k_final<<<NN / 8, 256>>>(nodes, b1, gamma, beta, out);
}

// round 16
// speedup vs baseline: 4.1618x; 1.0028x over previous
#include <cuda_runtime.h>
#include <cuda_fp16.h>
#include <cstdint>

#define NN 4096
#define DIMN 128
#define NH 8
#define ALPHA 0.2f

// ---------------- device scratch (no allocation allowed) -------------------
__device__ __half g_Whh[(size_t)NH * NN * DIMN];          // [h][n][d] fp16
__device__ float g_part[(size_t)NH * NN * DIMN];          // per-head GEMM partials
__device__ __half g_E1p[NH * NN];  // exp(min(f1,5.5))
__device__ __half g_E1n[NH * NN];  // exp(0.2*f1)
__device__ __half g_E2p[NH * NN];  // exp(min(f2,5.5))
__device__ __half g_E2n[NH * NN];  // exp(0.2*f2)
__device__ unsigned int g_maskx[(size_t)NN * (NN / 2)];   // 16-bit AND masks, packed x2

// ---------------- helpers ---------------------------------------------------
__device__ __forceinline__ uint32_t smem_u32(const void* p) {
    uint32_t a;
    asm("{ .reg .u64 t; cvta.to.shared.u64 t, %1; cvt.u32.u64 %0, t; }" : "=r"(a) : "l"(p));
    return a;
}
__device__ __forceinline__ void ldsm4(uint32_t& r0, uint32_t& r1, uint32_t& r2,
                                      uint32_t& r3, uint32_t addr) {
    asm volatile("ldmatrix.sync.aligned.m8n8.x4.shared.b16 {%0,%1,%2,%3}, [%4];"
                 : "=r"(r0), "=r"(r1), "=r"(r2), "=r"(r3) : "r"(addr));
}
__device__ __forceinline__ void ldsm4t(uint32_t& r0, uint32_t& r1, uint32_t& r2,
                                       uint32_t& r3, uint32_t addr) {
    asm volatile("ldmatrix.sync.aligned.m8n8.x4.trans.shared.b16 {%0,%1,%2,%3}, [%4];"
                 : "=r"(r0), "=r"(r1), "=r"(r2), "=r"(r3) : "r"(addr));
}
__device__ __forceinline__ void mma16816(float* c, const uint32_t* a,
                                         uint32_t b0, uint32_t b1) {
    asm volatile(
        "mma.sync.aligned.m16n8k16.row.col.f32.f16.f16.f32 "
        "{%0,%1,%2,%3}, {%4,%5,%6,%7}, {%8,%9}, {%0,%1,%2,%3};"
        : "+f"(c[0]), "+f"(c[1]), "+f"(c[2]), "+f"(c[3])
        : "r"(a[0]), "r"(a[1]), "r"(a[2]), "r"(a[3]), "r"(b0), "r"(b1));
}
__device__ __forceinline__ uint32_t h2mulmax(uint32_t e1p, uint32_t e1n,
                                             uint32_t e2p, uint32_t e2n,
                                             uint32_t msk) {
    __half2 u = __hmul2(*(__half2*)&e1p, *(__half2*)&e2p);
    __half2 v = __hmul2(*(__half2*)&e1n, *(__half2*)&e2n);
    __half2 m = __hmax2(u, v);
    return (*(uint32_t*)&m) & msk;
}

// ---------------------------------------------------------------------------
// adj -> packed 16-bit AND masks
// ---------------------------------------------------------------------------
__global__ __launch_bounds__(256) void k_mask(const int* __restrict__ adj) {
    size_t idx = (size_t)blockIdx.x * 256 + threadIdx.x;
    int2 a = ((const int2*)adj)[idx];
    g_maskx[idx] = (a.x > 0 ? 0x0000FFFFu : 0u) | (a.y > 0 ? 0xFFFF0000u : 0u);
}

// ---------------------------------------------------------------------------
// Kernel 1 (HMMA): Wh[h] = nodes @ W[h] in fp16 tensor cores.
// ---------------------------------------------------------------------------
#define WH_SMB 32768
#define WH_SMTOT 65536

__global__ void __launch_bounds__(256, 2) k_wh_mma(const float* __restrict__ nodes,
                                                   const float* __restrict__ W,
                                                   const float* __restrict__ a1,
                                                   const float* __restrict__ a2) {
    extern __shared__ char sm[];
    const uint32_t smb = smem_u32(sm);
    const int tid  = threadIdx.x;
    const int lane = tid & 31;
    const int wid  = tid >> 5;
    const int h  = blockIdx.y;
    const int i0 = blockIdx.x * 128;

    // ---- load A (nodes) and B (W[h]) as fp16, swizzled 256B rows ----
    {
        const int drow = tid >> 1;
        const int cb = (tid & 1) * 64;
        const float* ap = nodes + (size_t)(i0 + drow) * DIMN + cb;
        const float* bp = W + ((size_t)h * DIMN + drow) * DIMN + cb;
#pragma unroll
        for (int c = 0; c < 16; c++) {
            const uint32_t off = (uint32_t)(cb + c * 4) * 2;
            const uint32_t ch = off >> 4, wi = off & 15;
            const uint32_t sw = ((ch ^ ((drow & 7) << 1)) << 4) + wi;
            float4 fa = *(const float4*)(ap + c * 4);
            __half2 a0 = __floats2half2_rn(fa.x, fa.y);
            __half2 a1h = __floats2half2_rn(fa.z, fa.w);
            *(uint2*)(sm + drow * 256 + sw) =
                make_uint2(*(uint32_t*)&a0, *(uint32_t*)&a1h);
            float4 fb = *(const float4*)(bp + c * 4);
            __half2 b0 = __floats2half2_rn(fb.x, fb.y);
            __half2 b1h = __floats2half2_rn(fb.z, fb.w);
            *(uint2*)(sm + WH_SMB + drow * 256 + sw) =
                make_uint2(*(uint32_t*)&b0, *(uint32_t*)&b1h);
        }
    }
    __syncthreads();

    // ---- MMA 128x128x128 ----
    const int m0  = (wid & 3) * 32;
    const int n0w = (wid >> 2) * 64;
    float acc[2][8][4];
#pragma unroll
    for (int mi = 0; mi < 2; mi++)
#pragma unroll
        for (int t = 0; t < 8; t++)
#pragma unroll
            for (int q = 0; q < 4; q++) acc[mi][t][q] = 0.f;

#pragma unroll
    for (int k0 = 0; k0 < 128; k0 += 16) {
        uint32_t a[2][4];
#pragma unroll
        for (int mi = 0; mi < 2; mi++) {
            int rowA = m0 + mi * 16 + (lane & 15);
            int chA  = (k0 >> 3) + (lane >> 4);
            ldsm4(a[mi][0], a[mi][1], a[mi][2], a[mi][3],
                  smb + rowA * 256 + ((chA ^ ((rowA & 7) << 1)) << 4));
        }
        uint32_t b[4][4];
#pragma unroll
        for (int nt = 0; nt < 4; nt++) {
            int rowB = k0 + (lane & 15);
            int chB  = (n0w >> 3) + nt * 2 + (lane >> 4);
            ldsm4t(b[nt][0], b[nt][1], b[nt][2], b[nt][3],
                   smb + WH_SMB + rowB * 256 + ((chB ^ ((rowB & 7) << 1)) << 4));
        }
#pragma unroll
        for (int mi = 0; mi < 2; mi++)
#pragma unroll
            for (int nt = 0; nt < 4; nt++) {
                mma16816(acc[mi][nt * 2 + 0], a[mi], b[nt][0], b[nt][1]);
                mma16816(acc[mi][nt * 2 + 1], a[mi], b[nt][2], b[nt][3]);
            }
    }
    __syncthreads();  // A/B smem now free

    // ---- Wh -> gmem fp16 straight from fragments ----
#pragma unroll
    for (int mi = 0; mi < 2; mi++) {
        const int r1 = i0 + m0 + mi * 16 + (lane >> 2);
        __half* d1 = g_Whh + ((size_t)h * NN + r1) * DIMN + n0w + 2 * (lane & 3);
        __half* d2 = d1 + 8 * DIMN;
#pragma unroll
        for (int nt = 0; nt < 8; nt++) {
            __half2 hv1 = __floats2half2_rn(acc[mi][nt][0], acc[mi][nt][1]);
            __half2 hv2 = __floats2half2_rn(acc[mi][nt][2], acc[mi][nt][3]);
            *(__half2*)(d1 + nt * 8) = hv1;
            *(__half2*)(d2 + nt * 8) = hv2;
        }
    }

    // ---- f1/f2 fragment dot with a1/a2 ----
    {
        float f1p[2][2] = {{0.f, 0.f}, {0.f, 0.f}};
        float f2p[2][2] = {{0.f, 0.f}, {0.f, 0.f}};
#pragma unroll
        for (int nt = 0; nt < 8; nt++) {
            const int c0 = h * DIMN + n0w + nt * 8 + 2 * (lane & 3);
            float w1a = a1[c0], w1b = a1[c0 + 1];
            float w2a = a2[c0], w2b = a2[c0 + 1];
#pragma unroll
            for (int mi = 0; mi < 2; mi++) {
                f1p[mi][0] += acc[mi][nt][0] * w1a + acc[mi][nt][1] * w1b;
                f1p[mi][1] += acc[mi][nt][2] * w1a + acc[mi][nt][3] * w1b;
                f2p[mi][0] += acc[mi][nt][0] * w2a + acc[mi][nt][1] * w2b;
                f2p[mi][1] += acc[mi][nt][2] * w2a + acc[mi][nt][3] * w2b;
            }
        }
#pragma unroll
        for (int m = 1; m <= 2; m <<= 1) {
#pragma unroll
            for (int mi = 0; mi < 2; mi++)
#pragma unroll
                for (int hf = 0; hf < 2; hf++) {
                    f1p[mi][hf] += __shfl_xor_sync(0xffffffffu, f1p[mi][hf], m);
                    f2p[mi][hf] += __shfl_xor_sync(0xffffffffu, f2p[mi][hf], m);
                }
        }
        float* fbuf = (float*)sm;  // [grp*2 + which][128]
        if ((lane & 3) == 0) {
            const int grp = wid >> 2;
#pragma unroll
            for (int mi = 0; mi < 2; mi++)
#pragma unroll
                for (int hf = 0; hf < 2; hf++) {
                    const int r = m0 + mi * 16 + (lane >> 2) + hf * 8;
                    fbuf[(grp * 2 + 0) * 128 + r] = f1p[mi][hf];
                    fbuf[(grp * 2 + 1) * 128 + r] = f2p[mi][hf];
                }
        }
    }
    __syncthreads();
    if (tid < 128) {
        float* fbuf = (float*)sm;
        const float f1 = fbuf[0 * 128 + tid] + fbuf[2 * 128 + tid];
        const float f2 = fbuf[1 * 128 + tid] + fbuf[3 * 128 + tid];
        const int idx = h * NN + i0 + tid;
        g_E1p[idx] = __float2half(__expf(fminf(f1, 5.5f)));
        g_E1n[idx] = __float2half(__expf(ALPHA * f1));
        g_E2p[idx] = __float2half(__expf(fminf(f2, 5.5f)));
        g_E2n[idx] = __float2half(__expf(ALPHA * f2));
    }
}

// ---------------------------------------------------------------------------
// Kernel 2: attention + fused per-head linear1 partial GEMM.
// Den computed on fma pipe during p-gen (no ones-MMA): -11% tensor work.
// ---------------------------------------------------------------------------
#define SMA0 0
#define SMA1 16384
#define SMB0 32768
#define SMB1 49152
#define SM_DEN 65536
#define SM_TOTAL 66048

__global__ void __launch_bounds__(256, 2) k_attn_mma(const float* __restrict__ W1) {
    extern __shared__ char sm[];
    const uint32_t smb = smem_u32(sm);
    const int tid  = threadIdx.x;
    const int lane = tid & 31;
    const int wid  = tid >> 5;
    const int h  = blockIdx.y;
    const int i0 = blockIdx.x * 128;

    const int m0  = (wid & 3) * 32;   // warp row base
    const int n0w = (wid >> 2) * 64;  // warp col base

    float acc[2][8][4];
#pragma unroll
    for (int mi = 0; mi < 2; mi++)
#pragma unroll
        for (int t = 0; t < 8; t++)
#pragma unroll
            for (int q = 0; q < 4; q++) acc[mi][t][q] = 0.f;

    const int pr = tid >> 1;
    const int jh = (tid & 1) * 32;
    const uint32_t e1p_s = ((const unsigned short*)g_E1p)[h * NN + i0 + pr];
    const uint32_t e1n_s = ((const unsigned short*)g_E1n)[h * NN + i0 + pr];
    const uint32_t e1p2 = e1p_s | (e1p_s << 16);
    const uint32_t e1n2 = e1n_s | (e1n_s << 16);
    const uint4* mkrow = (const uint4*)(g_maskx + (size_t)(i0 + pr) * (NN / 2));

    const int wrow = tid >> 2;
    const int wcb  = (tid & 3) * 4;

    const uint32_t aOff[2] = {smb + SMA0, smb + SMA1};
    const uint32_t bOff[2] = {smb + SMB0, smb + SMB1};
    char* aPtr[2] = {sm + SMA0, sm + SMA1};
    char* bPtr[2] = {sm + SMB0, sm + SMB1};

    float dent = 0.f;  // fp32 den partial for (row pr, half jh)

    for (int t = 0; t < 64; t++) {
        const int s = t & 1;
        const int j0 = t * 64;

        // ---- load Wh tile [64 j][128 d], swizzled 16B chunks ----
        {
            const uint4* src = (const uint4*)((const char*)g_Whh +
                               ((size_t)h * NN + j0 + wrow) * (DIMN * 2));
            char* dstBase = bPtr[s] + wrow * 256;
#pragma unroll
            for (int c = 0; c < 4; c++) {
                int chunk = wcb + c;
                *(uint4*)(dstBase + ((chunk ^ ((wrow & 7) << 1)) << 4)) = src[chunk];
            }
        }
        // ---- generate p tile [128 i][64 j], swizzled; den on fma pipe ----
        {
            const uint4* mk4 = mkrow + ((j0 + jh) >> 3);
            const uint4* ep4 = (const uint4*)((const char*)g_E2p + ((size_t)h * NN + j0 + jh) * 2);
            const uint4* en4 = (const uint4*)((const char*)g_E2n + ((size_t)h * NN + j0 + jh) * 2);
            char* dstBase = aPtr[s] + pr * 128;
#pragma unroll
            for (int c = 0; c < 4; c++) {
                uint4 mk = mk4[c], ap = ep4[c], an = en4[c], o;
                o.x = h2mulmax(e1p2, e1n2, ap.x, an.x, mk.x);
                o.y = h2mulmax(e1p2, e1n2, ap.y, an.y, mk.y);
                o.z = h2mulmax(e1p2, e1n2, ap.z, an.z, mk.z);
                o.w = h2mulmax(e1p2, e1n2, ap.w, an.w, mk.w);
                float2 f0 = __half22float2(*(__half2*)&o.x);
                float2 f1 = __half22float2(*(__half2*)&o.y);
                float2 f2 = __half22float2(*(__half2*)&o.z);
                float2 f3 = __half22float2(*(__half2*)&o.w);
                dent += (f0.x + f0.y) + (f1.x + f1.y) + (f2.x + f2.y) + (f3.x + f3.y);
                int chunk = (tid & 1) * 4 + c;
                *(uint4*)(dstBase + ((chunk ^ (pr & 7)) << 4)) = o;
            }
        }
        __syncthreads();

        // ---- MMA over this tile: k = 64 in 4 steps of 16 ----
#pragma unroll
        for (int k0 = 0; k0 < 64; k0 += 16) {
            uint32_t a[2][4];
#pragma unroll
            for (int mi = 0; mi < 2; mi++) {
                int rowA = m0 + mi * 16 + (lane & 15);
                int chA  = (k0 >> 3) + (lane >> 4);
                ldsm4(a[mi][0], a[mi][1], a[mi][2], a[mi][3],
                      aOff[s] + rowA * 128 + ((chA ^ (rowA & 7)) << 4));
            }
            uint32_t b[4][4];
#pragma unroll
            for (int nt = 0; nt < 4; nt++) {
                int rowB = k0 + (lane & 15);
                int chB  = (n0w >> 3) + nt * 2 + (lane >> 4);
                ldsm4t(b[nt][0], b[nt][1], b[nt][2], b[nt][3],
                       bOff[s] + rowB * 256 + ((chB ^ ((rowB & 7) << 1)) << 4));
            }
#pragma unroll
            for (int mi = 0; mi < 2; mi++)
#pragma unroll
                for (int nt = 0; nt < 4; nt++) {
                    mma16816(acc[mi][nt * 2 + 0], a[mi], b[nt][0], b[nt][1]);
                    mma16816(acc[mi][nt * 2 + 1], a[mi], b[nt][2], b[nt][3]);
                }
        }
    }

    // ---- combine den across the 2 threads per row; publish to smem ----
    {
        dent += __shfl_xor_sync(0xffffffffu, dent, 1);
        float* denbuf = (float*)(sm + SM_DEN);
        denbuf[pr] = dent;  // both threads of the pair write the same value
    }
    __syncthreads();  // all warps done with main-loop buffers; den visible

    // ---- Phase 2a: normalize, ELU -> fp16 smem tile [128 r][128 d] at SMA0 ----
    {
        char* eluBase = sm + SMA0;
        const float* denbuf = (const float*)(sm + SM_DEN);
#pragma unroll
        for (int mi = 0; mi < 2; mi++) {
            const int r1 = m0 + mi * 16 + (lane >> 2);
            const int r2 = r1 + 8;
            const float inv1 = 1.0f / denbuf[r1];
            const float inv2 = 1.0f / denbuf[r2];
#pragma unroll
            for (int nt = 0; nt < 8; nt++) {
                float v0 = acc[mi][nt][0] * inv1;
                float v1 = acc[mi][nt][1] * inv1;
                float v2 = acc[mi][nt][2] * inv2;
                float v3 = acc[mi][nt][3] * inv2;
                v0 = v0 > 0.f ? v0 : expm1f(v0);
                v1 = v1 > 0.f ? v1 : expm1f(v1);
                v2 = v2 > 0.f ? v2 : expm1f(v2);
                v3 = v3 > 0.f ? v3 : expm1f(v3);
                const uint32_t off = (uint32_t)(n0w + nt * 8 + 2 * (lane & 3)) * 2;
                const uint32_t ch = off >> 4, wi = off & 15;
                __half2 hv1 = __floats2half2_rn(v0, v1);
                __half2 hv2 = __floats2half2_rn(v2, v3);
                *(__half2*)(eluBase + r1 * 256 + ((ch ^ ((r1 & 7) << 1)) << 4) + wi) = hv1;
                *(__half2*)(eluBase + r2 * 256 + ((ch ^ ((r2 & 7) << 1)) << 4) + wi) = hv2;
            }
        }
    }
    // ---- Phase 2b: W1 head-slice [128 d][128 out] fp32->fp16 smem at SMB0 ----
    {
        const int drow = tid >> 1;
        const int cb = (tid & 1) * 64;
        const float* w1p = W1 + ((size_t)(h * DIMN + drow)) * DIMN + cb;
        char* wBase = sm + SMB0;
#pragma unroll
        for (int c = 0; c < 16; c++) {
            float4 f = *(const float4*)(w1p + c * 4);
            __half2 h0 = __floats2half2_rn(f.x, f.y);
            __half2 h1 = __floats2half2_rn(f.z, f.w);
            const uint32_t off = (uint32_t)(cb + c * 4) * 2;
            const uint32_t ch = off >> 4, wi = off & 15;
            uint2 st = make_uint2(*(uint32_t*)&h0, *(uint32_t*)&h1);
            *(uint2*)(wBase + drow * 256 + ((ch ^ ((drow & 7) << 1)) << 4) + wi) = st;
        }
    }
    __syncthreads();

    // ---- Phase 2c: C2 = elu @ W1h  (128x128x128), write g_part[h] ----
    {
        float c2[2][8][4];
#pragma unroll
        for (int mi = 0; mi < 2; mi++)
#pragma unroll
            for (int t = 0; t < 8; t++)
#pragma unroll
                for (int q = 0; q < 4; q++) c2[mi][t][q] = 0.f;

        const uint32_t eluOff = smb + SMA0;
        const uint32_t wOff = smb + SMB0;
#pragma unroll
        for (int k0 = 0; k0 < 128; k0 += 16) {
            uint32_t a[2][4];
#pragma unroll
            for (int mi = 0; mi < 2; mi++) {
                int rowA = m0 + mi * 16 + (lane & 15);
                int chA  = (k0 >> 3) + (lane >> 4);
                ldsm4(a[mi][0], a[mi][1], a[mi][2], a[mi][3],
                      eluOff + rowA * 256 + ((chA ^ ((rowA & 7) << 1)) << 4));
            }
            uint32_t b[4][4];
#pragma unroll
            for (int nt = 0; nt < 4; nt++) {
                int rowB = k0 + (lane & 15);
                int chB  = (n0w >> 3) + nt * 2 + (lane >> 4);
                ldsm4t(b[nt][0], b[nt][1], b[nt][2], b[nt][3],
                       wOff + rowB * 256 + ((chB ^ ((rowB & 7) << 1)) << 4));
            }
#pragma unroll
            for (int mi = 0; mi < 2; mi++)
#pragma unroll
                for (int nt = 0; nt < 4; nt++) {
                    mma16816(c2[mi][nt * 2 + 0], a[mi], b[nt][0], b[nt][1]);
                    mma16816(c2[mi][nt * 2 + 1], a[mi], b[nt][2], b[nt][3]);
                }
        }
#pragma unroll
        for (int mi = 0; mi < 2; mi++) {
            const int r1 = i0 + m0 + mi * 16 + (lane >> 2);
            float* d1 = g_part + ((size_t)h * NN + r1) * DIMN + n0w + 2 * (lane & 3);
            float* d2 = d1 + 8 * DIMN;
#pragma unroll
            for (int nt = 0; nt < 8; nt++) {
                *(float2*)(d1 + nt * 8) = make_float2(c2[mi][nt][0], c2[mi][nt][1]);
                *(float2*)(d2 + nt * 8) = make_float2(c2[mi][nt][2], c2[mi][nt][3]);
            }
        }
    }
}

// ---------------------------------------------------------------------------
// Kernel 3: sum 8 head-partials + b1, elu, + nodes, layernorm -> out.
// ---------------------------------------------------------------------------
__global__ __launch_bounds__(256) void k_final(const float* __restrict__ nodes,
                                               const float* __restrict__ b1,
                                               const float* __restrict__ gamma,
                                               const float* __restrict__ beta,
                                               float* __restrict__ out) {
    const int lane = threadIdx.x & 31;
    const int row = blockIdx.x * 8 + (threadIdx.x >> 5);
    const int c = lane * 4;

    float4 s = make_float4(0.f, 0.f, 0.f, 0.f);
#pragma unroll
    for (int h = 0; h < NH; h++) {
        float4 p = *(const float4*)(g_part + ((size_t)h * NN + row) * DIMN + c);
        s.x += p.x; s.y += p.y; s.z += p.z; s.w += p.w;
    }
    float4 bb = *(const float4*)(b1 + c);
    float4 nd = *(const float4*)(nodes + (size_t)row * DIMN + c);

    float t[4];
    {
        float v;
        v = s.x + bb.x; v = v > 0.f ? v : expm1f(v); t[0] = nd.x + v;
        v = s.y + bb.y; v = v > 0.f ? v : expm1f(v); t[1] = nd.y + v;
        v = s.z + bb.z; v = v > 0.f ? v : expm1f(v); t[2] = nd.z + v;
        v = s.w + bb.w; v = v > 0.f ? v : expm1f(v); t[3] = nd.w + v;
    }
    float sum = t[0] + t[1] + t[2] + t[3];
#pragma unroll
    for (int m = 16; m >= 1; m >>= 1) sum += __shfl_xor_sync(0xffffffffu, sum, m);
    const float mu = sum * (1.0f / 128.0f);
    float q = 0.f;
#pragma unroll
    for (int j = 0; j < 4; j++) { float d = t[j] - mu; q += d * d; }
#pragma unroll
    for (int m = 16; m >= 1; m >>= 1) q += __shfl_xor_sync(0xffffffffu, q, m);
    const float rs = rsqrtf(q * (1.0f / 128.0f) + 1e-5f);

    float4 gg = *(const float4*)(gamma + c);
    float4 be = *(const float4*)(beta + c);
    float4 o;
    o.x = (t[0] - mu) * rs * gg.x + be.x;
    o.y = (t[1] - mu) * rs * gg.y + be.y;
    o.z = (t[2] - mu) * rs * gg.z + be.z;
    o.w = (t[3] - mu) * rs * gg.w + be.w;
    *(float4*)(out + (size_t)row * DIMN + c) = o;
}

// ---------------------------------------------------------------------------
extern "C" void kernel_launch(void* const* d_in, const int* in_sizes, int n_in,
                              void* d_out, int out_size) {
    const float* nodes = (const float*)d_in[0];
    const int*   adj   = (const int*)d_in[1];
    const float* W     = (const float*)d_in[2];
    const float* a1    = (const float*)d_in[3];
    const float* a2    = (const float*)d_in[4];
    const float* W1    = (const float*)d_in[5];
    const float* b1    = (const float*)d_in[6];
    const float* gamma = (const float*)d_in[7];
    const float* beta  = (const float*)d_in[8];
    float* out = (float*)d_out;

    cudaFuncSetAttribute(k_attn_mma, cudaFuncAttributeMaxDynamicSharedMemorySize, SM_TOTAL);
    cudaFuncSetAttribute(k_wh_mma, cudaFuncAttributeMaxDynamicSharedMemorySize, WH_SMTOT);

    k_mask<<<(NN * (NN / 2)) / 256, 256>>>(adj);
    dim3 gridWh(NN / 128, NH);
    k_wh_mma<<<gridWh, 256, WH_SMTOT>>>(nodes, W, a1, a2);
    dim3 gridAttn(NN / 128, NH);
    k_attn_mma<<<gridAttn, 256, SM_TOTAL>>>(W1);
    k_final<<<NN / 8, 256>>>(nodes, b1, gamma, beta, out);
}

// round 17
// speedup vs baseline: 4.8045x; 1.1544x over previous
#include <cuda_runtime.h>
#include <cuda_fp16.h>
#include <cstdint>

#define NN 4096
#define DIMN 128
#define NH 8
#define ALPHA 0.2f

// ---------------- device scratch (no allocation allowed) -------------------
__device__ __half g_Whh[(size_t)NH * NN * DIMN];          // [h][n][d] fp16
__device__ float g_part[(size_t)NH * NN * DIMN];          // per-head GEMM partials
__device__ __half g_E1p[NH * NN];  // exp(min(f1,5.5))
__device__ __half g_E1n[NH * NN];  // exp(0.2*f1)
__device__ __half g_E2p[NH * NN];  // exp(min(f2,5.5))
__device__ __half g_E2n[NH * NN];  // exp(0.2*f2)
__device__ unsigned int g_maskx[(size_t)NN * (NN / 2)];   // 16-bit AND masks, packed x2

// ---------------- helpers ---------------------------------------------------
__device__ __forceinline__ uint32_t smem_u32(const void* p) {
    uint32_t a;
    asm("{ .reg .u64 t; cvta.to.shared.u64 t, %1; cvt.u32.u64 %0, t; }" : "=r"(a) : "l"(p));
    return a;
}
__device__ __forceinline__ void ldsm4(uint32_t& r0, uint32_t& r1, uint32_t& r2,
                                      uint32_t& r3, uint32_t addr) {
    asm volatile("ldmatrix.sync.aligned.m8n8.x4.shared.b16 {%0,%1,%2,%3}, [%4];"
                 : "=r"(r0), "=r"(r1), "=r"(r2), "=r"(r3) : "r"(addr));
}
__device__ __forceinline__ void ldsm4t(uint32_t& r0, uint32_t& r1, uint32_t& r2,
                                       uint32_t& r3, uint32_t addr) {
    asm volatile("ldmatrix.sync.aligned.m8n8.x4.trans.shared.b16 {%0,%1,%2,%3}, [%4];"
                 : "=r"(r0), "=r"(r1), "=r"(r2), "=r"(r3) : "r"(addr));
}
__device__ __forceinline__ void mma16816(float* c, const uint32_t* a,
                                         uint32_t b0, uint32_t b1) {
    asm volatile(
        "mma.sync.aligned.m16n8k16.row.col.f32.f16.f16.f32 "
        "{%0,%1,%2,%3}, {%4,%5,%6,%7}, {%8,%9}, {%0,%1,%2,%3};"
        : "+f"(c[0]), "+f"(c[1]), "+f"(c[2]), "+f"(c[3])
        : "r"(a[0]), "r"(a[1]), "r"(a[2]), "r"(a[3]), "r"(b0), "r"(b1));
}
__device__ __forceinline__ uint32_t h2mulmax(uint32_t e1p, uint32_t e1n,
                                             uint32_t e2p, uint32_t e2n,
                                             uint32_t msk) {
    __half2 u = __hmul2(*(__half2*)&e1p, *(__half2*)&e2p);
    __half2 v = __hmul2(*(__half2*)&e1n, *(__half2*)&e2n);
    __half2 m = __hmax2(u, v);
    return (*(uint32_t*)&m) & msk;
}
__device__ __forceinline__ void cp_async16(uint32_t smem_addr, const void* gptr) {
    asm volatile("cp.async.cg.shared.global [%0], [%1], 16;"
                 :: "r"(smem_addr), "l"(gptr) : "memory");
}
#define CP_COMMIT() asm volatile("cp.async.commit_group;" ::: "memory")
#define CP_WAIT1()  asm volatile("cp.async.wait_group 1;" ::: "memory")
#define CP_WAIT0()  asm volatile("cp.async.wait_group 0;" ::: "memory")

// ---------------------------------------------------------------------------
// adj -> packed 16-bit AND masks
// ---------------------------------------------------------------------------
__global__ __launch_bounds__(256) void k_mask(const int* __restrict__ adj) {
    size_t idx = (size_t)blockIdx.x * 256 + threadIdx.x;
    int2 a = ((const int2*)adj)[idx];
    g_maskx[idx] = (a.x > 0 ? 0x0000FFFFu : 0u) | (a.y > 0 ? 0xFFFF0000u : 0u);
}

// ---------------------------------------------------------------------------
// Kernel 1 (HMMA): Wh[h] = nodes @ W[h] in fp16 tensor cores.
// ---------------------------------------------------------------------------
#define WH_SMB 32768
#define WH_SMTOT 65536

__global__ void __launch_bounds__(256, 2) k_wh_mma(const float* __restrict__ nodes,
                                                   const float* __restrict__ W,
                                                   const float* __restrict__ a1,
                                                   const float* __restrict__ a2) {
    extern __shared__ char sm[];
    const uint32_t smb = smem_u32(sm);
    const int tid  = threadIdx.x;
    const int lane = tid & 31;
    const int wid  = tid >> 5;
    const int h  = blockIdx.y;
    const int i0 = blockIdx.x * 128;

    // ---- load A (nodes) and B (W[h]) as fp16, swizzled 256B rows ----
    {
        const int drow = tid >> 1;
        const int cb = (tid & 1) * 64;
        const float* ap = nodes + (size_t)(i0 + drow) * DIMN + cb;
        const float* bp = W + ((size_t)h * DIMN + drow) * DIMN + cb;
#pragma unroll
        for (int c = 0; c < 16; c++) {
            const uint32_t off = (uint32_t)(cb + c * 4) * 2;
            const uint32_t ch = off >> 4, wi = off & 15;
            const uint32_t sw = ((ch ^ ((drow & 7) << 1)) << 4) + wi;
            float4 fa = *(const float4*)(ap + c * 4);
            __half2 a0 = __floats2half2_rn(fa.x, fa.y);
            __half2 a1h = __floats2half2_rn(fa.z, fa.w);
            *(uint2*)(sm + drow * 256 + sw) =
                make_uint2(*(uint32_t*)&a0, *(uint32_t*)&a1h);
            float4 fb = *(const float4*)(bp + c * 4);
            __half2 b0 = __floats2half2_rn(fb.x, fb.y);
            __half2 b1h = __floats2half2_rn(fb.z, fb.w);
            *(uint2*)(sm + WH_SMB + drow * 256 + sw) =
                make_uint2(*(uint32_t*)&b0, *(uint32_t*)&b1h);
        }
    }
    __syncthreads();

    // ---- MMA 128x128x128 ----
    const int m0  = (wid & 3) * 32;
    const int n0w = (wid >> 2) * 64;
    float acc[2][8][4];
#pragma unroll
    for (int mi = 0; mi < 2; mi++)
#pragma unroll
        for (int t = 0; t < 8; t++)
#pragma unroll
            for (int q = 0; q < 4; q++) acc[mi][t][q] = 0.f;

#pragma unroll
    for (int k0 = 0; k0 < 128; k0 += 16) {
        uint32_t a[2][4];
#pragma unroll
        for (int mi = 0; mi < 2; mi++) {
            int rowA = m0 + mi * 16 + (lane & 15);
            int chA  = (k0 >> 3) + (lane >> 4);
            ldsm4(a[mi][0], a[mi][1], a[mi][2], a[mi][3],
                  smb + rowA * 256 + ((chA ^ ((rowA & 7) << 1)) << 4));
        }
        uint32_t b[4][4];
#pragma unroll
        for (int nt = 0; nt < 4; nt++) {
            int rowB = k0 + (lane & 15);
            int chB  = (n0w >> 3) + nt * 2 + (lane >> 4);
            ldsm4t(b[nt][0], b[nt][1], b[nt][2], b[nt][3],
                   smb + WH_SMB + rowB * 256 + ((chB ^ ((rowB & 7) << 1)) << 4));
        }
#pragma unroll
        for (int mi = 0; mi < 2; mi++)
#pragma unroll
            for (int nt = 0; nt < 4; nt++) {
                mma16816(acc[mi][nt * 2 + 0], a[mi], b[nt][0], b[nt][1]);
                mma16816(acc[mi][nt * 2 + 1], a[mi], b[nt][2], b[nt][3]);
            }
    }
    __syncthreads();  // A/B smem now free

    // ---- Wh -> gmem fp16 straight from fragments ----
#pragma unroll
    for (int mi = 0; mi < 2; mi++) {
        const int r1 = i0 + m0 + mi * 16 + (lane >> 2);
        __half* d1 = g_Whh + ((size_t)h * NN + r1) * DIMN + n0w + 2 * (lane & 3);
        __half* d2 = d1 + 8 * DIMN;
#pragma unroll
        for (int nt = 0; nt < 8; nt++) {
            __half2 hv1 = __floats2half2_rn(acc[mi][nt][0], acc[mi][nt][1]);
            __half2 hv2 = __floats2half2_rn(acc[mi][nt][2], acc[mi][nt][3]);
            *(__half2*)(d1 + nt * 8) = hv1;
            *(__half2*)(d2 + nt * 8) = hv2;
        }
    }

    // ---- f1/f2 fragment dot with a1/a2 ----
    {
        float f1p[2][2] = {{0.f, 0.f}, {0.f, 0.f}};
        float f2p[2][2] = {{0.f, 0.f}, {0.f, 0.f}};
#pragma unroll
        for (int nt = 0; nt < 8; nt++) {
            const int c0 = h * DIMN + n0w + nt * 8 + 2 * (lane & 3);
            float w1a = a1[c0], w1b = a1[c0 + 1];
            float w2a = a2[c0], w2b = a2[c0 + 1];
#pragma unroll
            for (int mi = 0; mi < 2; mi++) {
                f1p[mi][0] += acc[mi][nt][0] * w1a + acc[mi][nt][1] * w1b;
                f1p[mi][1] += acc[mi][nt][2] * w1a + acc[mi][nt][3] * w1b;
                f2p[mi][0] += acc[mi][nt][0] * w2a + acc[mi][nt][1] * w2b;
                f2p[mi][1] += acc[mi][nt][2] * w2a + acc[mi][nt][3] * w2b;
            }
        }
#pragma unroll
        for (int m = 1; m <= 2; m <<= 1) {
#pragma unroll
            for (int mi = 0; mi < 2; mi++)
#pragma unroll
                for (int hf = 0; hf < 2; hf++) {
                    f1p[mi][hf] += __shfl_xor_sync(0xffffffffu, f1p[mi][hf], m);
                    f2p[mi][hf] += __shfl_xor_sync(0xffffffffu, f2p[mi][hf], m);
                }
        }
        float* fbuf = (float*)sm;  // [grp*2 + which][128]
        if ((lane & 3) == 0) {
            const int grp = wid >> 2;
#pragma unroll
            for (int mi = 0; mi < 2; mi++)
#pragma unroll
                for (int hf = 0; hf < 2; hf++) {
                    const int r = m0 + mi * 16 + (lane >> 2) + hf * 8;
                    fbuf[(grp * 2 + 0) * 128 + r] = f1p[mi][hf];
                    fbuf[(grp * 2 + 1) * 128 + r] = f2p[mi][hf];
                }
        }
    }
    __syncthreads();
    if (tid < 128) {
        float* fbuf = (float*)sm;
        const float f1 = fbuf[0 * 128 + tid] + fbuf[2 * 128 + tid];
        const float f2 = fbuf[1 * 128 + tid] + fbuf[3 * 128 + tid];
        const int idx = h * NN + i0 + tid;
        g_E1p[idx] = __float2half(__expf(fminf(f1, 5.5f)));
        g_E1n[idx] = __float2half(__expf(ALPHA * f1));
        g_E2p[idx] = __float2half(__expf(fminf(f2, 5.5f)));
        g_E2n[idx] = __float2half(__expf(ALPHA * f2));
    }
}

// ---------------------------------------------------------------------------
// Kernel 2: attention + fused per-head linear1 partial GEMM.
// Pipelined: Wh tiles via cp.async (3-stage ring, 1 ahead); mask words
// prefetched 1 tile ahead into registers; one barrier per tile.
// ---------------------------------------------------------------------------
#define SMA0 0
#define SMA1 16384
#define SMB0 32768                   // 3 stages of 16KB: 32768/49152/65536
#define SM_DEN (SMB0 + 3 * 16384)    // 81920
#define SM_TOTAL (SM_DEN + 512)      // 82432

__global__ void __launch_bounds__(256, 2) k_attn_mma(const float* __restrict__ W1) {
    extern __shared__ char sm[];
    const uint32_t smb = smem_u32(sm);
    const int tid  = threadIdx.x;
    const int lane = tid & 31;
    const int wid  = tid >> 5;
    const int h  = blockIdx.y;
    const int i0 = blockIdx.x * 128;

    const int m0  = (wid & 3) * 32;   // warp row base
    const int n0w = (wid >> 2) * 64;  // warp col base

    float acc[2][8][4];
#pragma unroll
    for (int mi = 0; mi < 2; mi++)
#pragma unroll
        for (int t = 0; t < 8; t++)
#pragma unroll
            for (int q = 0; q < 4; q++) acc[mi][t][q] = 0.f;

    const int pr = tid >> 1;
    const int jh = (tid & 1) * 32;
    const uint32_t e1p_s = ((const unsigned short*)g_E1p)[h * NN + i0 + pr];
    const uint32_t e1n_s = ((const unsigned short*)g_E1n)[h * NN + i0 + pr];
    const uint32_t e1p2 = e1p_s | (e1p_s << 16);
    const uint32_t e1n2 = e1n_s | (e1n_s << 16);
    const uint4* mkrow = (const uint4*)(g_maskx + (size_t)(i0 + pr) * (NN / 2));

    const int wrow = tid >> 2;
    const int wcb  = (tid & 3) * 4;

    const uint32_t aOff[2] = {smb + SMA0, smb + SMA1};
    char* aPtr[2] = {sm + SMA0, sm + SMA1};

    float dent = 0.f;  // fp32 den partial for (row pr, half jh)

    // ---- prologue: Wh tile 0 via cp.async; mask tile 0 into regs ----
    {
        const char* src = (const char*)g_Whh + ((size_t)h * NN + wrow) * (DIMN * 2);
        const uint32_t dstBase = smb + SMB0 + wrow * 256;
#pragma unroll
        for (int c = 0; c < 4; c++) {
            int chunk = wcb + c;
            cp_async16(dstBase + ((chunk ^ ((wrow & 7) << 1)) << 4), src + chunk * 16);
        }
        CP_COMMIT();
    }
    uint4 mkreg[4];
    {
        const uint4* mk4 = mkrow + (jh >> 3);
#pragma unroll
        for (int c = 0; c < 4; c++) mkreg[c] = mk4[c];
    }

    for (int t = 0; t < 64; t++) {
        const int s = t & 1;
        const int bs = t % 3;
        const int j0 = t * 64;

        // ---- issue Wh tile t+1 via cp.async into stage (t+1)%3 ----
        if (t + 1 < 64) {
            const char* src = (const char*)g_Whh +
                              ((size_t)h * NN + j0 + 64 + wrow) * (DIMN * 2);
            const uint32_t dstBase = smb + SMB0 + ((t + 1) % 3) * 16384 + wrow * 256;
#pragma unroll
            for (int c = 0; c < 4; c++) {
                int chunk = wcb + c;
                cp_async16(dstBase + ((chunk ^ ((wrow & 7) << 1)) << 4), src + chunk * 16);
            }
            CP_COMMIT();
        }

        // ---- generate p tile from prefetched masks + E2 (L1); den on fma ----
        {
            const uint4* ep4 = (const uint4*)((const char*)g_E2p + ((size_t)h * NN + j0 + jh) * 2);
            const uint4* en4 = (const uint4*)((const char*)g_E2n + ((size_t)h * NN + j0 + jh) * 2);
            char* dstBase = aPtr[s] + pr * 128;
#pragma unroll
            for (int c = 0; c < 4; c++) {
                uint4 mk = mkreg[c], ap = ep4[c], an = en4[c], o;
                o.x = h2mulmax(e1p2, e1n2, ap.x, an.x, mk.x);
                o.y = h2mulmax(e1p2, e1n2, ap.y, an.y, mk.y);
                o.z = h2mulmax(e1p2, e1n2, ap.z, an.z, mk.z);
                o.w = h2mulmax(e1p2, e1n2, ap.w, an.w, mk.w);
                float2 f0 = __half22float2(*(__half2*)&o.x);
                float2 f1 = __half22float2(*(__half2*)&o.y);
                float2 f2 = __half22float2(*(__half2*)&o.z);
                float2 f3 = __half22float2(*(__half2*)&o.w);
                dent += (f0.x + f0.y) + (f1.x + f1.y) + (f2.x + f2.y) + (f3.x + f3.y);
                int chunk = (tid & 1) * 4 + c;
                *(uint4*)(dstBase + ((chunk ^ (pr & 7)) << 4)) = o;
            }
        }
        // ---- prefetch mask tile t+1 (consumed after next barrier+MMA) ----
        if (t + 1 < 64) {
            const uint4* mkN = mkrow + ((j0 + 64 + jh) >> 3);
#pragma unroll
            for (int c = 0; c < 4; c++) mkreg[c] = mkN[c];
        }

        // ---- ensure Wh tile t has landed; keep t+1 in flight ----
        if (t + 1 < 64) { CP_WAIT1(); } else { CP_WAIT0(); }
        __syncthreads();

        // ---- MMA over this tile: k = 64 in 4 steps of 16 ----
        const uint32_t bOffS = smb + SMB0 + bs * 16384;
#pragma unroll
        for (int k0 = 0; k0 < 64; k0 += 16) {
            uint32_t a[2][4];
#pragma unroll
            for (int mi = 0; mi < 2; mi++) {
                int rowA = m0 + mi * 16 + (lane & 15);
                int chA  = (k0 >> 3) + (lane >> 4);
                ldsm4(a[mi][0], a[mi][1], a[mi][2], a[mi][3],
                      aOff[s] + rowA * 128 + ((chA ^ (rowA & 7)) << 4));
            }
            uint32_t b[4][4];
#pragma unroll
            for (int nt = 0; nt < 4; nt++) {
                int rowB = k0 + (lane & 15);
                int chB  = (n0w >> 3) + nt * 2 + (lane >> 4);
                ldsm4t(b[nt][0], b[nt][1], b[nt][2], b[nt][3],
                       bOffS + rowB * 256 + ((chB ^ ((rowB & 7) << 1)) << 4));
            }
#pragma unroll
            for (int mi = 0; mi < 2; mi++)
#pragma unroll
                for (int nt = 0; nt < 4; nt++) {
                    mma16816(acc[mi][nt * 2 + 0], a[mi], b[nt][0], b[nt][1]);
                    mma16816(acc[mi][nt * 2 + 1], a[mi], b[nt][2], b[nt][3]);
                }
        }
    }

    // ---- combine den across the 2 threads per row; publish to smem ----
    {
        dent += __shfl_xor_sync(0xffffffffu, dent, 1);
        float* denbuf = (float*)(sm + SM_DEN);
        denbuf[pr] = dent;
    }
    __syncthreads();  // main-loop buffers free; den visible

    // ---- Phase 2a: normalize, ELU -> fp16 smem tile [128 r][128 d] at SMA0 ----
    {
        char* eluBase = sm + SMA0;
        const float* denbuf = (const float*)(sm + SM_DEN);
#pragma unroll
        for (int mi = 0; mi < 2; mi++) {
            const int r1 = m0 + mi * 16 + (lane >> 2);
            const int r2 = r1 + 8;
            const float inv1 = 1.0f / denbuf[r1];
            const float inv2 = 1.0f / denbuf[r2];
#pragma unroll
            for (int nt = 0; nt < 8; nt++) {
                float v0 = acc[mi][nt][0] * inv1;
                float v1 = acc[mi][nt][1] * inv1;
                float v2 = acc[mi][nt][2] * inv2;
                float v3 = acc[mi][nt][3] * inv2;
                v0 = v0 > 0.f ? v0 : expm1f(v0);
                v1 = v1 > 0.f ? v1 : expm1f(v1);
                v2 = v2 > 0.f ? v2 : expm1f(v2);
                v3 = v3 > 0.f ? v3 : expm1f(v3);
                const uint32_t off = (uint32_t)(n0w + nt * 8 + 2 * (lane & 3)) * 2;
                const uint32_t ch = off >> 4, wi = off & 15;
                __half2 hv1 = __floats2half2_rn(v0, v1);
                __half2 hv2 = __floats2half2_rn(v2, v3);
                *(__half2*)(eluBase + r1 * 256 + ((ch ^ ((r1 & 7) << 1)) << 4) + wi) = hv1;
                *(__half2*)(eluBase + r2 * 256 + ((ch ^ ((r2 & 7) << 1)) << 4) + wi) = hv2;
            }
        }
    }
    // ---- Phase 2b: W1 head-slice [128 d][128 out] fp32->fp16 smem at SMB0 ----
    {
        const int drow = tid >> 1;
        const int cb = (tid & 1) * 64;
        const float* w1p = W1 + ((size_t)(h * DIMN + drow)) * DIMN + cb;
        char* wBase = sm + SMB0;
#pragma unroll
        for (int c = 0; c < 16; c++) {
            float4 f = *(const float4*)(w1p + c * 4);
            __half2 h0 = __floats2half2_rn(f.x, f.y);
            __half2 h1 = __floats2half2_rn(f.z, f.w);
            const uint32_t off = (uint32_t)(cb + c * 4) * 2;
            const uint32_t ch = off >> 4, wi = off & 15;
            uint2 st = make_uint2(*(uint32_t*)&h0, *(uint32_t*)&h1);
            *(uint2*)(wBase + drow * 256 + ((ch ^ ((drow & 7) << 1)) << 4) + wi) = st;
        }
    }
    __syncthreads();

    // ---- Phase 2c: C2 = elu @ W1h  (128x128x128), write g_part[h] ----
    {
        float c2[2][8][4];
#pragma unroll
        for (int mi = 0; mi < 2; mi++)
#pragma unroll
            for (int t = 0; t < 8; t++)
#pragma unroll
                for (int q = 0; q < 4; q++) c2[mi][t][q] = 0.f;

        const uint32_t eluOff = smb + SMA0;
        const uint32_t wOff = smb + SMB0;
#pragma unroll
        for (int k0 = 0; k0 < 128; k0 += 16) {
            uint32_t a[2][4];
#pragma unroll
            for (int mi = 0; mi < 2; mi++) {
                int rowA = m0 + mi * 16 + (lane & 15);
                int chA  = (k0 >> 3) + (lane >> 4);
                ldsm4(a[mi][0], a[mi][1], a[mi][2], a[mi][3],
                      eluOff + rowA * 256 + ((chA ^ ((rowA & 7) << 1)) << 4));
            }
            uint32_t b[4][4];
#pragma unroll
            for (int nt = 0; nt < 4; nt++) {
                int rowB = k0 + (lane & 15);
                int chB  = (n0w >> 3) + nt * 2 + (lane >> 4);
                ldsm4t(b[nt][0], b[nt][1], b[nt][2], b[nt][3],
                       wOff + rowB * 256 + ((chB ^ ((rowB & 7) << 1)) << 4));
            }
#pragma unroll
            for (int mi = 0; mi < 2; mi++)
#pragma unroll
                for (int nt = 0; nt < 4; nt++) {
                    mma16816(c2[mi][nt * 2 + 0], a[mi], b[nt][0], b[nt][1]);
                    mma16816(c2[mi][nt * 2 + 1], a[mi], b[nt][2], b[nt][3]);
                }
        }
#pragma unroll
        for (int mi = 0; mi < 2; mi++) {
            const int r1 = i0 + m0 + mi * 16 + (lane >> 2);
            float* d1 = g_part + ((size_t)h * NN + r1) * DIMN + n0w + 2 * (lane & 3);
            float* d2 = d1 + 8 * DIMN;
#pragma unroll
            for (int nt = 0; nt < 8; nt++) {
                *(float2*)(d1 + nt * 8) = make_float2(c2[mi][nt][0], c2[mi][nt][1]);
                *(float2*)(d2 + nt * 8) = make_float2(c2[mi][nt][2], c2[mi][nt][3]);
            }
        }
    }
}

// ---------------------------------------------------------------------------
// Kernel 3: sum 8 head-partials + b1, elu, + nodes, layernorm -> out.
// ---------------------------------------------------------------------------
__global__ __launch_bounds__(256) void k_final(const float* __restrict__ nodes,
                                               const float* __restrict__ b1,
                                               const float* __restrict__ gamma,
                                               const float* __restrict__ beta,
                                               float* __restrict__ out) {
    const int lane = threadIdx.x & 31;
    const int row = blockIdx.x * 8 + (threadIdx.x >> 5);
    const int c = lane * 4;

    float4 s = make_float4(0.f, 0.f, 0.f, 0.f);
#pragma unroll
    for (int h = 0; h < NH; h++) {
        float4 p = *(const float4*)(g_part + ((size_t)h * NN + row) * DIMN + c);
        s.x += p.x; s.y += p.y; s.z += p.z; s.w += p.w;
    }
    float4 bb = *(const float4*)(b1 + c);
    float4 nd = *(const float4*)(nodes + (size_t)row * DIMN + c);

    float t[4];
    {
        float v;
        v = s.x + bb.x; v = v > 0.f ? v : expm1f(v); t[0] = nd.x + v;
        v = s.y + bb.y; v = v > 0.f ? v : expm1f(v); t[1] = nd.y + v;
        v = s.z + bb.z; v = v > 0.f ? v : expm1f(v); t[2] = nd.z + v;
        v = s.w + bb.w; v = v > 0.f ? v : expm1f(v); t[3] = nd.w + v;
    }
    float sum = t[0] + t[1] + t[2] + t[3];
#pragma unroll
    for (int m = 16; m >= 1; m >>= 1) sum += __shfl_xor_sync(0xffffffffu, sum, m);
    const float mu = sum * (1.0f / 128.0f);
    float q = 0.f;
#pragma unroll
    for (int j = 0; j < 4; j++) { float d = t[j] - mu; q += d * d; }
#pragma unroll
    for (int m = 16; m >= 1; m >>= 1) q += __shfl_xor_sync(0xffffffffu, q, m);
    const float rs = rsqrtf(q * (1.0f / 128.0f) + 1e-5f);

    float4 gg = *(const float4*)(gamma + c);
    float4 be = *(const float4*)(beta + c);
    float4 o;
    o.x = (t[0] - mu) * rs * gg.x + be.x;
    o.y = (t[1] - mu) * rs * gg.y + be.y;
    o.z = (t[2] - mu) * rs * gg.z + be.z;
    o.w = (t[3] - mu) * rs * gg.w + be.w;
    *(float4*)(out + (size_t)row * DIMN + c) = o;
}

// ---------------------------------------------------------------------------
extern "C" void kernel_launch(void* const* d_in, const int* in_sizes, int n_in,
                              void* d_out, int out_size) {
    const float* nodes = (const float*)d_in[0];
    const int*   adj   = (const int*)d_in[1];
    const float* W     = (const float*)d_in[2];
    const float* a1    = (const float*)d_in[3];
    const float* a2    = (const float*)d_in[4];
    const float* W1    = (const float*)d_in[5];
    const float* b1    = (const float*)d_in[6];
    const float* gamma = (const float*)d_in[7];
    const float* beta  = (const float*)d_in[8];
    float* out = (float*)d_out;

    cudaFuncSetAttribute(k_attn_mma, cudaFuncAttributeMaxDynamicSharedMemorySize, SM_TOTAL);
    cudaFuncSetAttribute(k_wh_mma, cudaFuncAttributeMaxDynamicSharedMemorySize, WH_SMTOT);

    k_mask<<<(NN * (NN / 2)) / 256, 256>>>(adj);
    dim3 gridWh(NN / 128, NH);
    k_wh_mma<<<gridWh, 256, WH_SMTOT>>>(nodes, W, a1, a2);
    dim3 gridAttn(NN / 128, NH);
    k_attn_mma<<<gridAttn, 256, SM_TOTAL>>>(W1);
    k_final<<<NN / 8, 256>>>(nodes, b1, gamma, beta, out);
}